// round 2
// baseline (speedup 1.0000x reference)
#include <cuda_runtime.h>
#include <cuda_bf16.h>
#include <stdint.h>

#define N_NODES  100000
#define N_EDGES  3200000
#define IN_FEAT  512
#define HIDDEN   64
#define N_GRAPHS 2048

// ---------------- scratch (static device allocations) ----------------
__device__ float g_h1[(size_t)N_NODES * HIDDEN];   // dinv-prescaled X@W1
__device__ int   g_rp[N_NODES + 1];                // CSR row ptr (by dst)
__device__ int   g_cnt[N_NODES];                   // histogram, then reused as fill cursor
__device__ int   g_ci[N_EDGES];                    // CSR col idx (src)
__device__ float g_dinv[N_NODES];
__device__ float g_t[N_NODES];                     // per-node layer2 scalar
__device__ float g_w2f[HIDDEN];                    // W2 @ fc_w
__device__ float g_bb;                             // b2 . fc_w
__device__ float g_gsum[N_GRAPHS];
__device__ float g_gcnt[N_GRAPHS];
__device__ int   g_bsum[128];                      // scan block sums
__device__ int   g_is64;                           // 1 if index buffers are int64

// ---------------- dtype detection ----------------
// int64 little-endian non-negative values < 2^31 => every odd int32 word is 0.
// A genuine int32 edge list has random node ids at odd positions (never all 0).
__global__ void k_detect(const int* __restrict__ ei32) {
    if (threadIdx.x != 0 || blockIdx.x != 0) return;
    int s = 1;
    for (int i = 1; i < 512; i += 2) {
        if (ei32[i] != 0) { s = 0; break; }
    }
    g_is64 = s;
}

__device__ __forceinline__ int idx_at(const void* p, long long i) {
    if (g_is64) return (int)((const long long*)p)[i];
    return ((const int*)p)[i];
}

// ---------------- init / histogram ----------------
__global__ void k_zero() {
    int i = blockIdx.x * blockDim.x + threadIdx.x;
    if (i < N_NODES) g_cnt[i] = 0;
    if (i < N_GRAPHS) { g_gsum[i] = 0.f; g_gcnt[i] = 0.f; }
}

__global__ void k_count(const void* __restrict__ ei) {
    int e = blockIdx.x * blockDim.x + threadIdx.x;
    if (e >= N_EDGES) return;
    int d = idx_at(ei, (long long)N_EDGES + e);   // dst row
    atomicAdd(&g_cnt[d], 1);
}

// ---------------- exclusive scan over g_cnt -> g_rp ----------------
__global__ void k_scan_a() {                       // 98 blocks x 1024
    __shared__ int ws[32];
    int tid = threadIdx.x;
    int idx = blockIdx.x * 1024 + tid;
    int v = (idx < N_NODES) ? g_cnt[idx] : 0;
    int lane = tid & 31, w = tid >> 5;
    int s = v;
    #pragma unroll
    for (int o = 16; o; o >>= 1) s += __shfl_xor_sync(0xffffffffu, s, o);
    if (lane == 0) ws[w] = s;
    __syncthreads();
    if (w == 0) {
        int x = ws[lane];
        #pragma unroll
        for (int o = 16; o; o >>= 1) x += __shfl_xor_sync(0xffffffffu, x, o);
        if (lane == 0) g_bsum[blockIdx.x] = x;
    }
}

__global__ void k_scan_b(int nblocks) {            // 1 block, serial (98 elems)
    if (threadIdx.x == 0) {
        int run = 0;
        for (int i = 0; i < nblocks; i++) { int t = g_bsum[i]; g_bsum[i] = run; run += t; }
    }
}

__global__ void k_scan_c() {                       // 98 blocks x 1024
    __shared__ int ws[32];
    int tid = threadIdx.x;
    int idx = blockIdx.x * 1024 + tid;
    int v = (idx < N_NODES) ? g_cnt[idx] : 0;
    int lane = tid & 31, w = tid >> 5;
    int inc = v;
    #pragma unroll
    for (int o = 1; o < 32; o <<= 1) {
        int n = __shfl_up_sync(0xffffffffu, inc, o);
        if (lane >= o) inc += n;
    }
    if (lane == 31) ws[w] = inc;
    __syncthreads();
    if (w == 0) {
        int x = ws[lane];
        #pragma unroll
        for (int o = 1; o < 32; o <<= 1) {
            int n = __shfl_up_sync(0xffffffffu, x, o);
            if (lane >= o) x += n;
        }
        ws[lane] = x;
    }
    __syncthreads();
    int off = (w > 0) ? ws[w - 1] : 0;
    int excl = off + inc - v;
    if (idx < N_NODES) g_rp[idx] = g_bsum[blockIdx.x] + excl;
    if (idx == 0 && blockIdx.x == 0) g_rp[N_NODES] = N_EDGES;
}

// dinv from rp diffs (+1 self loop); reset cursor for fill
__global__ void k_dinv_cursor() {
    int i = blockIdx.x * blockDim.x + threadIdx.x;
    if (i >= N_NODES) return;
    int s = g_rp[i];
    int deg = g_rp[i + 1] - s + 1;
    g_dinv[i] = rsqrtf((float)deg);
    g_cnt[i] = s;       // reuse as fill cursor
}

__global__ void k_fill(const void* __restrict__ ei) {
    int e = blockIdx.x * blockDim.x + threadIdx.x;
    if (e >= N_EDGES) return;
    int s = idx_at(ei, e);
    int d = idx_at(ei, (long long)N_EDGES + e);
    int pos = atomicAdd(&g_cnt[d], 1);
    g_ci[pos] = s;
}

// w2f = W2 @ fc_w ; bb = b2 . fc_w
__global__ void k_fold(const float* __restrict__ W2, const float* __restrict__ b2,
                       const float* __restrict__ fcw) {
    int f = threadIdx.x;
    if (f < HIDDEN) {
        float a = 0.f;
        #pragma unroll 8
        for (int j = 0; j < HIDDEN; j++) a += W2[f * HIDDEN + j] * fcw[j];
        g_w2f[f] = a;
    }
    if (f == 0) {
        float a = 0.f;
        for (int j = 0; j < HIDDEN; j++) a += b2[j] * fcw[j];
        g_bb = a;
    }
}

// ---------------- GEMM1: h1 = dinv * (X @ W1) ----------------
// 128x64 tile, K-tile 16, 256 threads, 8x4 per-thread microtile.
#define BM 128
#define BN 64
#define BK 16
__global__ __launch_bounds__(256) void k_gemm1(const float* __restrict__ X,
                                               const float* __restrict__ W) {
    __shared__ float As[BK][BM + 4];
    __shared__ float Bs[BK][BN];
    int tid = threadIdx.x;
    int block_row = blockIdx.x * BM;
    int tx = tid & 15;          // col group (4 cols)
    int ty = tid >> 4;          // row group (8 rows)
    float acc[8][4];
    #pragma unroll
    for (int i = 0; i < 8; i++)
        #pragma unroll
        for (int j = 0; j < 4; j++) acc[i][j] = 0.f;

    for (int k0 = 0; k0 < IN_FEAT; k0 += BK) {
        // A: 128x16 = 512 float4 slots, 2 per thread
        #pragma unroll
        for (int i = 0; i < 2; i++) {
            int slot = tid * 2 + i;
            int r = slot >> 2;
            int k4 = slot & 3;
            int grow = block_row + r;
            float4 v = make_float4(0.f, 0.f, 0.f, 0.f);
            if (grow < N_NODES)
                v = *(const float4*)&X[(size_t)grow * IN_FEAT + k0 + k4 * 4];
            As[k4 * 4 + 0][r] = v.x;
            As[k4 * 4 + 1][r] = v.y;
            As[k4 * 4 + 2][r] = v.z;
            As[k4 * 4 + 3][r] = v.w;
        }
        // B: 16x64 = 256 float4 slots, 1 per thread
        {
            int r = tid >> 4;
            int c4 = tid & 15;
            *(float4*)&Bs[r][c4 * 4] = *(const float4*)&W[(size_t)(k0 + r) * BN + c4 * 4];
        }
        __syncthreads();
        #pragma unroll
        for (int kk = 0; kk < BK; kk++) {
            float a[8];
            float4 a0 = *(const float4*)&As[kk][ty * 8];
            float4 a1 = *(const float4*)&As[kk][ty * 8 + 4];
            a[0]=a0.x; a[1]=a0.y; a[2]=a0.z; a[3]=a0.w;
            a[4]=a1.x; a[5]=a1.y; a[6]=a1.z; a[7]=a1.w;
            float4 bv = *(const float4*)&Bs[kk][tx * 4];
            float b[4] = {bv.x, bv.y, bv.z, bv.w};
            #pragma unroll
            for (int i = 0; i < 8; i++)
                #pragma unroll
                for (int j = 0; j < 4; j++)
                    acc[i][j] = fmaf(a[i], b[j], acc[i][j]);
        }
        __syncthreads();
    }
    #pragma unroll
    for (int i = 0; i < 8; i++) {
        int grow = block_row + ty * 8 + i;
        if (grow < N_NODES) {
            float d = g_dinv[grow];
            float4 o = make_float4(acc[i][0] * d, acc[i][1] * d, acc[i][2] * d, acc[i][3] * d);
            *(float4*)&g_h1[(size_t)grow * HIDDEN + tx * 4] = o;
        }
    }
}

// ---------------- layer1 aggregation fused with layer2 fold ----------------
// warp per node: acc = h1[self] + sum_{src in N(i)} h1[src]
// t_i = dinv_i * dot(relu(dinv_i*acc + b1), w2f)
__global__ __launch_bounds__(256) void k_agg1(const float* __restrict__ b1) {
    int gw = (blockIdx.x * blockDim.x + threadIdx.x) >> 5;
    int lane = threadIdx.x & 31;
    if (gw >= N_NODES) return;
    const float2* hp = (const float2*)g_h1;
    float2 acc = hp[(size_t)gw * 32 + lane];     // self loop (prescaled by dinv)
    int s = g_rp[gw], e = g_rp[gw + 1];
    for (int base = s; base < e; base += 32) {
        int c = -1;
        if (base + lane < e) c = g_ci[base + lane];
        int m = min(32, e - base);
        for (int j = 0; j < m; j++) {
            int src = __shfl_sync(0xffffffffu, c, j);
            float2 v = hp[(size_t)src * 32 + lane];
            acc.x += v.x;
            acc.y += v.y;
        }
    }
    float di = g_dinv[gw];
    float y0 = fmaxf(fmaf(di, acc.x, b1[2 * lane]), 0.f);
    float y1 = fmaxf(fmaf(di, acc.y, b1[2 * lane + 1]), 0.f);
    float p = y0 * g_w2f[2 * lane] + y1 * g_w2f[2 * lane + 1];
    #pragma unroll
    for (int o = 16; o; o >>= 1) p += __shfl_xor_sync(0xffffffffu, p, o);
    if (lane == 0) g_t[gw] = di * p;
}

// ---------------- scalar layer-2 aggregation + mean-pool accumulate ----------------
__global__ void k_agg2_pool(const void* __restrict__ batch) {
    int i = blockIdx.x * blockDim.x + threadIdx.x;
    if (i >= N_NODES) return;
    float s = g_t[i];                 // self loop
    int e0 = g_rp[i], e1 = g_rp[i + 1];
    for (int e = e0; e < e1; e++) s += g_t[g_ci[e]];
    float si = g_dinv[i] * s + g_bb;
    int b = idx_at(batch, i);
    atomicAdd(&g_gsum[b], si);
    atomicAdd(&g_gcnt[b], 1.0f);
}

__global__ void k_final(const float* __restrict__ fcb, float* __restrict__ out) {
    int g = blockIdx.x * blockDim.x + threadIdx.x;
    if (g >= N_GRAPHS) return;
    out[g] = g_gsum[g] / fmaxf(g_gcnt[g], 1.0f) + fcb[0];
}

// ---------------- launch ----------------
extern "C" void kernel_launch(void* const* d_in, const int* in_sizes, int n_in,
                              void* d_out, int out_size) {
    const float* x   = (const float*)d_in[0];
    const void*  ei  = d_in[1];
    const void*  bat = d_in[2];
    // inputs: x, edge_index, batch, [num_graphs], W1, b1, W2, b2, fc_w, fc_b
    int base = (in_sizes[3] == IN_FEAT * HIDDEN) ? 3 : 4;
    const float* W1  = (const float*)d_in[base + 0];
    const float* b1  = (const float*)d_in[base + 1];
    const float* W2  = (const float*)d_in[base + 2];
    const float* b2  = (const float*)d_in[base + 3];
    const float* fcw = (const float*)d_in[base + 4];
    const float* fcb = (const float*)d_in[base + 5];
    float* out = (float*)d_out;

    const int SCAN_BLOCKS = (N_NODES + 1023) / 1024;   // 98

    k_detect<<<1, 32>>>((const int*)ei);
    k_zero<<<(N_NODES + 255) / 256, 256>>>();
    k_count<<<(N_EDGES + 255) / 256, 256>>>(ei);
    k_scan_a<<<SCAN_BLOCKS, 1024>>>();
    k_scan_b<<<1, 32>>>(SCAN_BLOCKS);
    k_scan_c<<<SCAN_BLOCKS, 1024>>>();
    k_dinv_cursor<<<(N_NODES + 255) / 256, 256>>>();
    k_fold<<<1, 64>>>(W2, b2, fcw);
    k_fill<<<(N_EDGES + 255) / 256, 256>>>(ei);
    k_gemm1<<<(N_NODES + BM - 1) / BM, 256>>>(x, W1);
    k_agg1<<<(N_NODES * 32 + 255) / 256, 256>>>(b1);
    k_agg2_pool<<<(N_NODES + 255) / 256, 256>>>(bat);
    k_final<<<(N_GRAPHS + 255) / 256, 256>>>(fcb, out);
}

// round 5
// speedup vs baseline: 1.3049x; 1.3049x over previous
#include <cuda_runtime.h>
#include <cuda_bf16.h>
#include <stdint.h>

#define N_NODES  100000
#define N_EDGES  3200000
#define IN_FEAT  512
#define HIDDEN   64
#define N_GRAPHS 2048

// ---------------- scratch (static device allocations) ----------------
__device__ float g_h1[(size_t)N_NODES * HIDDEN];   // dinv-prescaled X@W1
__device__ int   g_rp[N_NODES + 1];                // CSR row ptr (by dst)
__device__ int   g_cnt[N_NODES];                   // histogram, then reused as fill cursor
__device__ int   g_ci[N_EDGES];                    // CSR col idx (src)
__device__ float g_dinv[N_NODES];
__device__ float g_t[N_NODES];                     // per-node layer2 scalar
__device__ float g_w2f[HIDDEN];                    // W2 @ fc_w
__device__ float g_bb;                             // b2 . fc_w
__device__ float g_gsum[N_GRAPHS];
__device__ float g_gcnt[N_GRAPHS];
__device__ int   g_bsum[128];                      // scan block sums
__device__ int   g_is64;                           // 1 if index buffers are int64

// ---------------- dtype detection ----------------
__global__ void k_detect(const int* __restrict__ ei32) {
    if (threadIdx.x != 0 || blockIdx.x != 0) return;
    int s = 1;
    for (int i = 1; i < 512; i += 2) {
        if (ei32[i] != 0) { s = 0; break; }
    }
    g_is64 = s;
}

__device__ __forceinline__ int idx_at(const void* p, long long i) {
    if (g_is64) return (int)((const long long*)p)[i];
    return ((const int*)p)[i];
}

// ---------------- init / histogram ----------------
__global__ void k_zero() {
    int i = blockIdx.x * blockDim.x + threadIdx.x;
    if (i < N_NODES) g_cnt[i] = 0;
    if (i < N_GRAPHS) { g_gsum[i] = 0.f; g_gcnt[i] = 0.f; }
}

__global__ void k_count(const void* __restrict__ ei) {
    int e = blockIdx.x * blockDim.x + threadIdx.x;
    if (e >= N_EDGES) return;
    int d = idx_at(ei, (long long)N_EDGES + e);   // dst row
    atomicAdd(&g_cnt[d], 1);
}

// ---------------- exclusive scan over g_cnt -> g_rp ----------------
__global__ void k_scan_a() {
    __shared__ int ws[32];
    int tid = threadIdx.x;
    int idx = blockIdx.x * 1024 + tid;
    int v = (idx < N_NODES) ? g_cnt[idx] : 0;
    int lane = tid & 31, w = tid >> 5;
    int s = v;
    #pragma unroll
    for (int o = 16; o; o >>= 1) s += __shfl_xor_sync(0xffffffffu, s, o);
    if (lane == 0) ws[w] = s;
    __syncthreads();
    if (w == 0) {
        int x = ws[lane];
        #pragma unroll
        for (int o = 16; o; o >>= 1) x += __shfl_xor_sync(0xffffffffu, x, o);
        if (lane == 0) g_bsum[blockIdx.x] = x;
    }
}

__global__ void k_scan_b(int nblocks) {
    if (threadIdx.x == 0) {
        int run = 0;
        for (int i = 0; i < nblocks; i++) { int t = g_bsum[i]; g_bsum[i] = run; run += t; }
    }
}

__global__ void k_scan_c() {
    __shared__ int ws[32];
    int tid = threadIdx.x;
    int idx = blockIdx.x * 1024 + tid;
    int v = (idx < N_NODES) ? g_cnt[idx] : 0;
    int lane = tid & 31, w = tid >> 5;
    int inc = v;
    #pragma unroll
    for (int o = 1; o < 32; o <<= 1) {
        int n = __shfl_up_sync(0xffffffffu, inc, o);
        if (lane >= o) inc += n;
    }
    if (lane == 31) ws[w] = inc;
    __syncthreads();
    if (w == 0) {
        int x = ws[lane];
        #pragma unroll
        for (int o = 1; o < 32; o <<= 1) {
            int n = __shfl_up_sync(0xffffffffu, x, o);
            if (lane >= o) x += n;
        }
        ws[lane] = x;
    }
    __syncthreads();
    int off = (w > 0) ? ws[w - 1] : 0;
    int excl = off + inc - v;
    if (idx < N_NODES) g_rp[idx] = g_bsum[blockIdx.x] + excl;
    if (idx == 0 && blockIdx.x == 0) g_rp[N_NODES] = N_EDGES;
}

__global__ void k_dinv_cursor() {
    int i = blockIdx.x * blockDim.x + threadIdx.x;
    if (i >= N_NODES) return;
    int s = g_rp[i];
    int deg = g_rp[i + 1] - s + 1;
    g_dinv[i] = rsqrtf((float)deg);
    g_cnt[i] = s;       // reuse as fill cursor
}

__global__ void k_fill(const void* __restrict__ ei) {
    int e = blockIdx.x * blockDim.x + threadIdx.x;
    if (e >= N_EDGES) return;
    int s = idx_at(ei, e);
    int d = idx_at(ei, (long long)N_EDGES + e);
    int pos = atomicAdd(&g_cnt[d], 1);
    g_ci[pos] = s;
}

__global__ void k_fold(const float* __restrict__ W2, const float* __restrict__ b2,
                       const float* __restrict__ fcw) {
    int f = threadIdx.x;
    if (f < HIDDEN) {
        float a = 0.f;
        #pragma unroll 8
        for (int j = 0; j < HIDDEN; j++) a += W2[f * HIDDEN + j] * fcw[j];
        g_w2f[f] = a;
    }
    if (f == 0) {
        float a = 0.f;
        for (int j = 0; j < HIDDEN; j++) a += b2[j] * fcw[j];
        g_bb = a;
    }
}

// ======================================================================
// GEMM1 via mma.sync tf32 (sm_80+ baseline ISA, works on plain sm_103)
// h1 = dinv * (X @ W1).  CTA tile 128x64, 8 warps (4M x 2N), warp 32x32.
// K chunks of 32; fragments m16n8k8.
// ======================================================================
#define APITCH 36
#define BPITCH 36

__device__ __forceinline__ uint32_t f2tf32(float f) {
    uint32_t u;
    asm("cvt.rna.tf32.f32 %0, %1;" : "=r"(u) : "f"(f));
    return u;
}

__global__ __launch_bounds__(256) void k_gemm_mma(const float* __restrict__ X,
                                                  const float* __restrict__ W) {
    __shared__ uint32_t As[128 * APITCH];   // [m][k], tf32 bits
    __shared__ uint32_t Bs[64 * BPITCH];    // [n][k] (W transposed), tf32 bits

    int tid = threadIdx.x;
    int lane = tid & 31;
    int wid = tid >> 5;
    int wm = wid & 3;          // 0..3  -> M offset wm*32
    int wn = wid >> 2;         // 0..1  -> N offset wn*32
    int block_row = blockIdx.x * 128;

    float acc[2][4][4];
    #pragma unroll
    for (int mi = 0; mi < 2; mi++)
        #pragma unroll
        for (int ni = 0; ni < 4; ni++)
            #pragma unroll
            for (int r = 0; r < 4; r++) acc[mi][ni][r] = 0.f;

    int lq = lane >> 2;        // 0..7
    int lr = lane & 3;         // 0..3

    for (int ch = 0; ch < 16; ch++) {
        // ---- fill A: 128 rows x 32 k (4 float4 slots per thread) ----
        #pragma unroll
        for (int i = 0; i < 4; i++) {
            int slot = tid + 256 * i;          // 0..1023
            int row = slot >> 3;
            int c4 = slot & 7;
            float4 v = make_float4(0.f, 0.f, 0.f, 0.f);
            int gr = block_row + row;
            if (gr < N_NODES)
                v = *(const float4*)&X[(size_t)gr * IN_FEAT + ch * 32 + c4 * 4];
            uint32_t* ap = &As[row * APITCH + c4 * 4];
            ap[0] = f2tf32(v.x); ap[1] = f2tf32(v.y);
            ap[2] = f2tf32(v.z); ap[3] = f2tf32(v.w);
        }
        // ---- fill B transposed: Bs[n][k] = W[ch*32+k][n] ----
        // 32 k x 64 n = 512 float4 loads -> 2 per thread
        #pragma unroll
        for (int i = 0; i < 2; i++) {
            int slot = tid + 256 * i;          // 0..511
            int k = slot >> 4;                 // 0..31
            int n16 = slot & 15;               // 0..15 -> 4 n's each
            float4 v = *(const float4*)&W[(size_t)(ch * 32 + k) * HIDDEN + n16 * 4];
            Bs[(n16 * 4 + 0) * BPITCH + k] = f2tf32(v.x);
            Bs[(n16 * 4 + 1) * BPITCH + k] = f2tf32(v.y);
            Bs[(n16 * 4 + 2) * BPITCH + k] = f2tf32(v.z);
            Bs[(n16 * 4 + 3) * BPITCH + k] = f2tf32(v.w);
        }
        __syncthreads();

        #pragma unroll
        for (int kk = 0; kk < 32; kk += 8) {
            uint32_t a[2][4], b[4][2];
            #pragma unroll
            for (int mi = 0; mi < 2; mi++) {
                const uint32_t* ar = &As[(wm * 32 + mi * 16 + lq) * APITCH + kk + lr];
                a[mi][0] = ar[0];
                a[mi][1] = ar[8 * APITCH];
                a[mi][2] = ar[4];
                a[mi][3] = ar[8 * APITCH + 4];
            }
            #pragma unroll
            for (int ni = 0; ni < 4; ni++) {
                const uint32_t* br = &Bs[(wn * 32 + ni * 8 + lq) * BPITCH + kk + lr];
                b[ni][0] = br[0];
                b[ni][1] = br[4];
            }
            #pragma unroll
            for (int mi = 0; mi < 2; mi++)
                #pragma unroll
                for (int ni = 0; ni < 4; ni++) {
                    asm volatile(
                        "mma.sync.aligned.m16n8k8.row.col.f32.tf32.tf32.f32 "
                        "{%0,%1,%2,%3}, {%4,%5,%6,%7}, {%8,%9}, {%0,%1,%2,%3};"
                        : "+f"(acc[mi][ni][0]), "+f"(acc[mi][ni][1]),
                          "+f"(acc[mi][ni][2]), "+f"(acc[mi][ni][3])
                        : "r"(a[mi][0]), "r"(a[mi][1]), "r"(a[mi][2]), "r"(a[mi][3]),
                          "r"(b[ni][0]), "r"(b[ni][1]));
                }
        }
        __syncthreads();
    }

    // ---- epilogue: scale by dinv, store to g_h1 ----
    #pragma unroll
    for (int mi = 0; mi < 2; mi++) {
        int r0 = block_row + wm * 32 + mi * 16 + lq;
        int r1 = r0 + 8;
        float d0 = (r0 < N_NODES) ? g_dinv[r0] : 0.f;
        float d1 = (r1 < N_NODES) ? g_dinv[r1] : 0.f;
        #pragma unroll
        for (int ni = 0; ni < 4; ni++) {
            int col = wn * 32 + ni * 8 + lr * 2;
            if (r0 < N_NODES) {
                float2 o = make_float2(acc[mi][ni][0] * d0, acc[mi][ni][1] * d0);
                *(float2*)&g_h1[(size_t)r0 * HIDDEN + col] = o;
            }
            if (r1 < N_NODES) {
                float2 o = make_float2(acc[mi][ni][2] * d1, acc[mi][ni][3] * d1);
                *(float2*)&g_h1[(size_t)r1 * HIDDEN + col] = o;
            }
        }
    }
}

// ---------------- layer1 aggregation fused with layer2 fold ----------------
__global__ __launch_bounds__(256) void k_agg1(const float* __restrict__ b1) {
    int gw = (blockIdx.x * blockDim.x + threadIdx.x) >> 5;
    int lane = threadIdx.x & 31;
    if (gw >= N_NODES) return;
    const float2* hp = (const float2*)g_h1;
    float2 acc = hp[(size_t)gw * 32 + lane];     // self loop (prescaled by dinv)
    int s = g_rp[gw], e = g_rp[gw + 1];
    for (int base = s; base < e; base += 32) {
        int c = -1;
        if (base + lane < e) c = g_ci[base + lane];
        int m = min(32, e - base);
        for (int j = 0; j < m; j++) {
            int src = __shfl_sync(0xffffffffu, c, j);
            float2 v = hp[(size_t)src * 32 + lane];
            acc.x += v.x;
            acc.y += v.y;
        }
    }
    float di = g_dinv[gw];
    float y0 = fmaxf(fmaf(di, acc.x, b1[2 * lane]), 0.f);
    float y1 = fmaxf(fmaf(di, acc.y, b1[2 * lane + 1]), 0.f);
    float p = y0 * g_w2f[2 * lane] + y1 * g_w2f[2 * lane + 1];
    #pragma unroll
    for (int o = 16; o; o >>= 1) p += __shfl_xor_sync(0xffffffffu, p, o);
    if (lane == 0) g_t[gw] = di * p;
}

// ---------------- scalar layer-2 aggregation + mean-pool accumulate ----------------
__global__ void k_agg2_pool(const void* __restrict__ batch) {
    int i = blockIdx.x * blockDim.x + threadIdx.x;
    if (i >= N_NODES) return;
    float s = g_t[i];                 // self loop
    int e0 = g_rp[i], e1 = g_rp[i + 1];
    for (int e = e0; e < e1; e++) s += g_t[g_ci[e]];
    float si = g_dinv[i] * s + g_bb;
    int b = idx_at(batch, i);
    atomicAdd(&g_gsum[b], si);
    atomicAdd(&g_gcnt[b], 1.0f);
}

__global__ void k_final(const float* __restrict__ fcb, float* __restrict__ out) {
    int g = blockIdx.x * blockDim.x + threadIdx.x;
    if (g >= N_GRAPHS) return;
    out[g] = g_gsum[g] / fmaxf(g_gcnt[g], 1.0f) + fcb[0];
}

// ---------------- launch ----------------
extern "C" void kernel_launch(void* const* d_in, const int* in_sizes, int n_in,
                              void* d_out, int out_size) {
    const float* x   = (const float*)d_in[0];
    const void*  ei  = d_in[1];
    const void*  bat = d_in[2];
    int base = (in_sizes[3] == IN_FEAT * HIDDEN) ? 3 : 4;
    const float* W1  = (const float*)d_in[base + 0];
    const float* b1  = (const float*)d_in[base + 1];
    const float* W2  = (const float*)d_in[base + 2];
    const float* b2  = (const float*)d_in[base + 3];
    const float* fcw = (const float*)d_in[base + 4];
    const float* fcb = (const float*)d_in[base + 5];
    float* out = (float*)d_out;

    const int SCAN_BLOCKS = (N_NODES + 1023) / 1024;   // 98

    k_detect<<<1, 32>>>((const int*)ei);
    k_zero<<<(N_NODES + 255) / 256, 256>>>();
    k_count<<<(N_EDGES + 255) / 256, 256>>>(ei);
    k_scan_a<<<SCAN_BLOCKS, 1024>>>();
    k_scan_b<<<1, 32>>>(SCAN_BLOCKS);
    k_scan_c<<<SCAN_BLOCKS, 1024>>>();
    k_dinv_cursor<<<(N_NODES + 255) / 256, 256>>>();
    k_fold<<<1, 64>>>(W2, b2, fcw);
    k_fill<<<(N_EDGES + 255) / 256, 256>>>(ei);
    k_gemm_mma<<<(N_NODES + 127) / 128, 256>>>(x, W1);
    k_agg1<<<(N_NODES * 32 + 255) / 256, 256>>>(b1);
    k_agg2_pool<<<(N_NODES + 255) / 256, 256>>>(bat);
    k_final<<<(N_GRAPHS + 255) / 256, 256>>>(fcb, out);
}

// round 6
// speedup vs baseline: 1.4029x; 1.0750x over previous
#include <cuda_runtime.h>
#include <cuda_fp16.h>
#include <cuda_bf16.h>
#include <stdint.h>

#define N_NODES  100000
#define N_EDGES  3200000
#define IN_FEAT  512
#define HIDDEN   64
#define N_GRAPHS 2048

// ---------------- scratch (static device allocations) ----------------
__device__ __align__(16) __half g_h1[(size_t)N_NODES * HIDDEN]; // dinv-prescaled X@W1, fp16
__device__ int   g_rp[N_NODES + 1];                // CSR row ptr (by dst)
__device__ int   g_cnt[N_NODES];                   // histogram, then reused as fill cursor
__device__ int   g_ci[N_EDGES];                    // CSR col idx (src)
__device__ float g_dinv[N_NODES];
__device__ float g_t[N_NODES];                     // per-node layer2 scalar
__device__ float g_w2f[HIDDEN];                    // W2 @ fc_w
__device__ float g_bb;                             // b2 . fc_w
__device__ float g_gsum[N_GRAPHS];
__device__ float g_gcnt[N_GRAPHS];
__device__ int   g_bsum[128];                      // scan block sums
__device__ int   g_is64;                           // 1 if index buffers are int64

// ---------------- dtype detection ----------------
__global__ void k_detect(const int* __restrict__ ei32) {
    if (threadIdx.x != 0 || blockIdx.x != 0) return;
    int s = 1;
    for (int i = 1; i < 512; i += 2) {
        if (ei32[i] != 0) { s = 0; break; }
    }
    g_is64 = s;
}

__device__ __forceinline__ int idx_at(const void* p, long long i) {
    if (g_is64) return (int)((const long long*)p)[i];
    return ((const int*)p)[i];
}

// ---------------- init / histogram ----------------
__global__ void k_zero() {
    int i = blockIdx.x * blockDim.x + threadIdx.x;
    if (i < N_NODES) g_cnt[i] = 0;
    if (i < N_GRAPHS) { g_gsum[i] = 0.f; g_gcnt[i] = 0.f; }
}

__global__ void k_count(const void* __restrict__ ei) {
    int e = blockIdx.x * blockDim.x + threadIdx.x;
    if (e >= N_EDGES) return;
    int d = idx_at(ei, (long long)N_EDGES + e);   // dst row
    atomicAdd(&g_cnt[d], 1);
}

// ---------------- exclusive scan over g_cnt -> g_rp ----------------
__global__ void k_scan_a() {
    __shared__ int ws[32];
    int tid = threadIdx.x;
    int idx = blockIdx.x * 1024 + tid;
    int v = (idx < N_NODES) ? g_cnt[idx] : 0;
    int lane = tid & 31, w = tid >> 5;
    int s = v;
    #pragma unroll
    for (int o = 16; o; o >>= 1) s += __shfl_xor_sync(0xffffffffu, s, o);
    if (lane == 0) ws[w] = s;
    __syncthreads();
    if (w == 0) {
        int x = ws[lane];
        #pragma unroll
        for (int o = 16; o; o >>= 1) x += __shfl_xor_sync(0xffffffffu, x, o);
        if (lane == 0) g_bsum[blockIdx.x] = x;
    }
}

__global__ void k_scan_b(int nblocks) {
    if (threadIdx.x == 0) {
        int run = 0;
        for (int i = 0; i < nblocks; i++) { int t = g_bsum[i]; g_bsum[i] = run; run += t; }
    }
}

__global__ void k_scan_c() {
    __shared__ int ws[32];
    int tid = threadIdx.x;
    int idx = blockIdx.x * 1024 + tid;
    int v = (idx < N_NODES) ? g_cnt[idx] : 0;
    int lane = tid & 31, w = tid >> 5;
    int inc = v;
    #pragma unroll
    for (int o = 1; o < 32; o <<= 1) {
        int n = __shfl_up_sync(0xffffffffu, inc, o);
        if (lane >= o) inc += n;
    }
    if (lane == 31) ws[w] = inc;
    __syncthreads();
    if (w == 0) {
        int x = ws[lane];
        #pragma unroll
        for (int o = 1; o < 32; o <<= 1) {
            int n = __shfl_up_sync(0xffffffffu, x, o);
            if (lane >= o) x += n;
        }
        ws[lane] = x;
    }
    __syncthreads();
    int off = (w > 0) ? ws[w - 1] : 0;
    int excl = off + inc - v;
    if (idx < N_NODES) g_rp[idx] = g_bsum[blockIdx.x] + excl;
    if (idx == 0 && blockIdx.x == 0) g_rp[N_NODES] = N_EDGES;
}

__global__ void k_dinv_cursor() {
    int i = blockIdx.x * blockDim.x + threadIdx.x;
    if (i >= N_NODES) return;
    int s = g_rp[i];
    int deg = g_rp[i + 1] - s + 1;
    g_dinv[i] = rsqrtf((float)deg);
    g_cnt[i] = s;       // reuse as fill cursor
}

__global__ void k_fill(const void* __restrict__ ei) {
    int e = blockIdx.x * blockDim.x + threadIdx.x;
    if (e >= N_EDGES) return;
    int s = idx_at(ei, e);
    int d = idx_at(ei, (long long)N_EDGES + e);
    int pos = atomicAdd(&g_cnt[d], 1);
    g_ci[pos] = s;
}

__global__ void k_fold(const float* __restrict__ W2, const float* __restrict__ b2,
                       const float* __restrict__ fcw) {
    int f = threadIdx.x;
    if (f < HIDDEN) {
        float a = 0.f;
        #pragma unroll 8
        for (int j = 0; j < HIDDEN; j++) a += W2[f * HIDDEN + j] * fcw[j];
        g_w2f[f] = a;
    }
    if (f == 0) {
        float a = 0.f;
        for (int j = 0; j < HIDDEN; j++) a += b2[j] * fcw[j];
        g_bb = a;
    }
}

// ======================================================================
// GEMM1 via mma.sync tf32 + cp.async double-buffered pipeline
// h1(fp16) = dinv * (X @ W1). CTA 128x64, 8 warps (4M x 2N), warp 32x32.
// A staged raw-fp32 via cp.async with 16B XOR swizzle; B staged with cvt.rna.
// ======================================================================
#define BPITCH 36
// dynamic smem: A 2*128*32 words = 8192 w (32KB), B 2*64*36 = 4608 w (18KB)
#define GEMM_SMEM_BYTES ((8192 + 4608) * 4)

__device__ __forceinline__ uint32_t f2tf32(float f) {
    uint32_t u;
    asm("cvt.rna.tf32.f32 %0, %1;" : "=r"(u) : "f"(f));
    return u;
}

__device__ __forceinline__ void cp16(uint32_t saddr, const void* g) {
    asm volatile("cp.async.cg.shared.global [%0], [%1], 16;" :: "r"(saddr), "l"(g));
}

__global__ __launch_bounds__(256) void k_gemm_mma(const float* __restrict__ X,
                                                  const float* __restrict__ W) {
    extern __shared__ uint32_t dsm[];
    uint32_t* As = dsm;            // [buf][row][32 w], 16B-group XOR swizzle
    uint32_t* Bs = dsm + 8192;     // [buf][n][BPITCH]
    uint32_t as_base = (uint32_t)__cvta_generic_to_shared(As);

    int tid = threadIdx.x;
    int lane = tid & 31;
    int wid = tid >> 5;
    int wm = wid & 3;
    int wn = wid >> 2;
    int block_row = blockIdx.x * 128;

    float acc[2][4][4];
    #pragma unroll
    for (int mi = 0; mi < 2; mi++)
        #pragma unroll
        for (int ni = 0; ni < 4; ni++)
            #pragma unroll
            for (int r = 0; r < 4; r++) acc[mi][ni][r] = 0.f;

    int lq = lane >> 2;
    int lr = lane & 3;

    // ---- stage fill helpers (inlined manually via macros/lambdas) ----
    auto issueA = [&](int ch, int buf) {
        #pragma unroll
        for (int i = 0; i < 4; i++) {
            int slot = tid + 256 * i;          // 0..1023
            int row = slot >> 3;
            int c4 = slot & 7;
            int sw = (c4 ^ (row & 7)) << 2;    // swizzled word-in-row
            uint32_t widx = buf * 4096 + row * 32 + sw;
            int gr = block_row + row;
            if (gr < N_NODES) {
                cp16(as_base + widx * 4, &X[(size_t)gr * IN_FEAT + ch * 32 + c4 * 4]);
            } else {
                *(uint4*)&As[widx] = make_uint4(0, 0, 0, 0);
            }
        }
    };
    auto fillB = [&](int ch, int buf) {
        #pragma unroll
        for (int i = 0; i < 2; i++) {
            int slot = tid + 256 * i;          // 0..511
            int k = slot >> 4;
            int n16 = slot & 15;
            float4 v = *(const float4*)&W[(size_t)(ch * 32 + k) * HIDDEN + n16 * 4];
            uint32_t* bp = Bs + buf * (64 * BPITCH);
            bp[(n16 * 4 + 0) * BPITCH + k] = f2tf32(v.x);
            bp[(n16 * 4 + 1) * BPITCH + k] = f2tf32(v.y);
            bp[(n16 * 4 + 2) * BPITCH + k] = f2tf32(v.z);
            bp[(n16 * 4 + 3) * BPITCH + k] = f2tf32(v.w);
        }
    };

    issueA(0, 0);
    fillB(0, 0);
    asm volatile("cp.async.commit_group;");

    for (int ch = 0; ch < 16; ch++) {
        int buf = ch & 1;
        if (ch + 1 < 16) {
            issueA(ch + 1, buf ^ 1);
            fillB(ch + 1, buf ^ 1);
            asm volatile("cp.async.commit_group;");
            asm volatile("cp.async.wait_group 1;");
        } else {
            asm volatile("cp.async.wait_group 0;");
        }
        __syncthreads();

        const uint32_t* Ab = As + buf * 4096;
        const uint32_t* Bb = Bs + buf * (64 * BPITCH);

        #pragma unroll
        for (int kk = 0; kk < 32; kk += 8) {
            uint32_t a[2][4], b[4][2];
            int g0 = kk >> 2;                  // 16B group of low half
            #pragma unroll
            for (int mi = 0; mi < 2; mi++) {
                int r0 = wm * 32 + mi * 16 + lq;
                int r1 = r0 + 8;
                int s0 = r0 & 7;               // == r1 & 7
                a[mi][0] = Ab[r0 * 32 + (((g0) ^ s0) << 2) + lr];
                a[mi][1] = Ab[r1 * 32 + (((g0) ^ s0) << 2) + lr];
                a[mi][2] = Ab[r0 * 32 + (((g0 + 1) ^ s0) << 2) + lr];
                a[mi][3] = Ab[r1 * 32 + (((g0 + 1) ^ s0) << 2) + lr];
            }
            #pragma unroll
            for (int ni = 0; ni < 4; ni++) {
                const uint32_t* br = &Bb[(wn * 32 + ni * 8 + lq) * BPITCH + kk + lr];
                b[ni][0] = br[0];
                b[ni][1] = br[4];
            }
            #pragma unroll
            for (int mi = 0; mi < 2; mi++)
                #pragma unroll
                for (int ni = 0; ni < 4; ni++) {
                    asm volatile(
                        "mma.sync.aligned.m16n8k8.row.col.f32.tf32.tf32.f32 "
                        "{%0,%1,%2,%3}, {%4,%5,%6,%7}, {%8,%9}, {%0,%1,%2,%3};"
                        : "+f"(acc[mi][ni][0]), "+f"(acc[mi][ni][1]),
                          "+f"(acc[mi][ni][2]), "+f"(acc[mi][ni][3])
                        : "r"(a[mi][0]), "r"(a[mi][1]), "r"(a[mi][2]), "r"(a[mi][3]),
                          "r"(b[ni][0]), "r"(b[ni][1]));
                }
        }
        __syncthreads();
    }

    // ---- epilogue: scale by dinv, store fp16 to g_h1 ----
    __half2* h1h = (__half2*)g_h1;
    #pragma unroll
    for (int mi = 0; mi < 2; mi++) {
        int r0 = block_row + wm * 32 + mi * 16 + lq;
        int r1 = r0 + 8;
        float d0 = (r0 < N_NODES) ? g_dinv[r0] : 0.f;
        float d1 = (r1 < N_NODES) ? g_dinv[r1] : 0.f;
        #pragma unroll
        for (int ni = 0; ni < 4; ni++) {
            int c2 = wn * 16 + ni * 4 + lr;    // half2 column index
            if (r0 < N_NODES)
                h1h[(size_t)r0 * 32 + c2] =
                    __floats2half2_rn(acc[mi][ni][0] * d0, acc[mi][ni][1] * d0);
            if (r1 < N_NODES)
                h1h[(size_t)r1 * 32 + c2] =
                    __floats2half2_rn(acc[mi][ni][2] * d1, acc[mi][ni][3] * d1);
        }
    }
}

// ---------------- layer1 aggregation fused with layer2 fold ----------------
__global__ __launch_bounds__(256) void k_agg1(const float* __restrict__ b1) {
    int gw = (blockIdx.x * blockDim.x + threadIdx.x) >> 5;
    int lane = threadIdx.x & 31;
    if (gw >= N_NODES) return;
    const __half2* hp = (const __half2*)g_h1;
    float2 acc = __half22float2(hp[(size_t)gw * 32 + lane]);   // self loop (prescaled)
    int s = g_rp[gw], e = g_rp[gw + 1];
    for (int base = s; base < e; base += 32) {
        int c = -1;
        if (base + lane < e) c = g_ci[base + lane];
        int m = min(32, e - base);
        for (int j = 0; j < m; j++) {
            int src = __shfl_sync(0xffffffffu, c, j);
            float2 v = __half22float2(hp[(size_t)src * 32 + lane]);
            acc.x += v.x;
            acc.y += v.y;
        }
    }
    float di = g_dinv[gw];
    float y0 = fmaxf(fmaf(di, acc.x, b1[2 * lane]), 0.f);
    float y1 = fmaxf(fmaf(di, acc.y, b1[2 * lane + 1]), 0.f);
    float p = y0 * g_w2f[2 * lane] + y1 * g_w2f[2 * lane + 1];
    #pragma unroll
    for (int o = 16; o; o >>= 1) p += __shfl_xor_sync(0xffffffffu, p, o);
    if (lane == 0) g_t[gw] = di * p;
}

// ---------------- scalar layer-2 aggregation + mean-pool accumulate ----------------
__global__ void k_agg2_pool(const void* __restrict__ batch) {
    int i = blockIdx.x * blockDim.x + threadIdx.x;
    if (i >= N_NODES) return;
    float s = g_t[i];                 // self loop
    int e0 = g_rp[i], e1 = g_rp[i + 1];
    for (int e = e0; e < e1; e++) s += g_t[g_ci[e]];
    float si = g_dinv[i] * s + g_bb;
    int b = idx_at(batch, i);
    atomicAdd(&g_gsum[b], si);
    atomicAdd(&g_gcnt[b], 1.0f);
}

__global__ void k_final(const float* __restrict__ fcb, float* __restrict__ out) {
    int g = blockIdx.x * blockDim.x + threadIdx.x;
    if (g >= N_GRAPHS) return;
    out[g] = g_gsum[g] / fmaxf(g_gcnt[g], 1.0f) + fcb[0];
}

// ---------------- launch ----------------
extern "C" void kernel_launch(void* const* d_in, const int* in_sizes, int n_in,
                              void* d_out, int out_size) {
    const float* x   = (const float*)d_in[0];
    const void*  ei  = d_in[1];
    const void*  bat = d_in[2];
    int base = (in_sizes[3] == IN_FEAT * HIDDEN) ? 3 : 4;
    const float* W1  = (const float*)d_in[base + 0];
    const float* b1  = (const float*)d_in[base + 1];
    const float* W2  = (const float*)d_in[base + 2];
    const float* b2  = (const float*)d_in[base + 3];
    const float* fcw = (const float*)d_in[base + 4];
    const float* fcb = (const float*)d_in[base + 5];
    float* out = (float*)d_out;

    const int SCAN_BLOCKS = (N_NODES + 1023) / 1024;   // 98

    cudaFuncSetAttribute(k_gemm_mma, cudaFuncAttributeMaxDynamicSharedMemorySize,
                         GEMM_SMEM_BYTES);

    k_detect<<<1, 32>>>((const int*)ei);
    k_zero<<<(N_NODES + 255) / 256, 256>>>();
    k_count<<<(N_EDGES + 255) / 256, 256>>>(ei);
    k_scan_a<<<SCAN_BLOCKS, 1024>>>();
    k_scan_b<<<1, 32>>>(SCAN_BLOCKS);
    k_scan_c<<<SCAN_BLOCKS, 1024>>>();
    k_dinv_cursor<<<(N_NODES + 255) / 256, 256>>>();
    k_fold<<<1, 64>>>(W2, b2, fcw);
    k_fill<<<(N_EDGES + 255) / 256, 256>>>(ei);
    k_gemm_mma<<<(N_NODES + 127) / 128, 256, GEMM_SMEM_BYTES>>>(x, W1);
    k_agg1<<<(N_NODES * 32 + 255) / 256, 256>>>(b1);
    k_agg2_pool<<<(N_NODES + 255) / 256, 256>>>(bat);
    k_final<<<(N_GRAPHS + 255) / 256, 256>>>(fcb, out);
}

// round 7
// speedup vs baseline: 1.5487x; 1.1040x over previous
#include <cuda_runtime.h>
#include <cuda_fp16.h>
#include <cuda_bf16.h>
#include <stdint.h>

#define N_NODES  100000
#define N_EDGES  3200000
#define IN_FEAT  512
#define HIDDEN   64
#define N_GRAPHS 2048

// ---------------- scratch (static device allocations) ----------------
__device__ __align__(16) __half g_h1[(size_t)N_NODES * HIDDEN]; // dinv-prescaled X@W1, fp16
__device__ int   g_rp[N_NODES + 1];                // CSR row ptr (by dst)
__device__ int   g_cnt[N_NODES];                   // in-degree histogram
__device__ int   g_cur[N_NODES];                   // fill cursor
__device__ int   g_ci[N_EDGES];                    // CSR col idx (src)
__device__ float g_dinv[N_NODES];
__device__ float g_t[N_NODES];                     // per-node layer2 scalar
__device__ float g_w2f[HIDDEN];                    // W2 @ fc_w
__device__ float g_bb;                             // b2 . fc_w
__device__ float g_gsum[N_GRAPHS];
__device__ float g_gcnt[N_GRAPHS];
__device__ int   g_bsum[128];                      // scan block sums
__device__ int   g_is64;                           // 1 if index buffers are int64
__device__ __align__(16) uint32_t g_w1t[(size_t)HIDDEN * IN_FEAT]; // W1^T in tf32 bits

// ---------------- dtype detection ----------------
__global__ void k_detect(const int* __restrict__ ei32) {
    if (threadIdx.x != 0 || blockIdx.x != 0) return;
    int s = 1;
    for (int i = 1; i < 512; i += 2) {
        if (ei32[i] != 0) { s = 0; break; }
    }
    g_is64 = s;
}

__device__ __forceinline__ int idx_at(const void* p, long long i) {
    if (g_is64) return (int)((const long long*)p)[i];
    return ((const int*)p)[i];
}

// ---------------- init / histogram ----------------
__global__ void k_zero() {
    int i = blockIdx.x * blockDim.x + threadIdx.x;
    if (i < N_NODES) g_cnt[i] = 0;
    if (i < N_GRAPHS) { g_gsum[i] = 0.f; g_gcnt[i] = 0.f; }
}

__global__ void k_count(const void* __restrict__ ei) {
    int e = blockIdx.x * blockDim.x + threadIdx.x;
    if (e >= N_EDGES) return;
    int d = idx_at(ei, (long long)N_EDGES + e);   // dst row
    atomicAdd(&g_cnt[d], 1);
}

// ---------------- exclusive scan over g_cnt -> g_rp ----------------
__global__ void k_scan_a() {
    __shared__ int ws[32];
    int tid = threadIdx.x;
    int idx = blockIdx.x * 1024 + tid;
    int v = (idx < N_NODES) ? g_cnt[idx] : 0;
    int lane = tid & 31, w = tid >> 5;
    int s = v;
    #pragma unroll
    for (int o = 16; o; o >>= 1) s += __shfl_xor_sync(0xffffffffu, s, o);
    if (lane == 0) ws[w] = s;
    __syncthreads();
    if (w == 0) {
        int x = ws[lane];
        #pragma unroll
        for (int o = 16; o; o >>= 1) x += __shfl_xor_sync(0xffffffffu, x, o);
        if (lane == 0) g_bsum[blockIdx.x] = x;
    }
}

__global__ void k_scan_b(int nblocks) {
    if (threadIdx.x == 0) {
        int run = 0;
        for (int i = 0; i < nblocks; i++) { int t = g_bsum[i]; g_bsum[i] = run; run += t; }
    }
}

__global__ void k_scan_c() {
    __shared__ int ws[32];
    int tid = threadIdx.x;
    int idx = blockIdx.x * 1024 + tid;
    int v = (idx < N_NODES) ? g_cnt[idx] : 0;
    int lane = tid & 31, w = tid >> 5;
    int inc = v;
    #pragma unroll
    for (int o = 1; o < 32; o <<= 1) {
        int n = __shfl_up_sync(0xffffffffu, inc, o);
        if (lane >= o) inc += n;
    }
    if (lane == 31) ws[w] = inc;
    __syncthreads();
    if (w == 0) {
        int x = ws[lane];
        #pragma unroll
        for (int o = 1; o < 32; o <<= 1) {
            int n = __shfl_up_sync(0xffffffffu, x, o);
            if (lane >= o) x += n;
        }
        ws[lane] = x;
    }
    __syncthreads();
    int off = (w > 0) ? ws[w - 1] : 0;
    int excl = off + inc - v;
    if (idx < N_NODES) { g_rp[idx] = g_bsum[blockIdx.x] + excl; g_cur[idx] = g_bsum[blockIdx.x] + excl; }
    if (idx == 0 && blockIdx.x == 0) g_rp[N_NODES] = N_EDGES;
}

// dinv straight from histogram (runs on side stream, before scan finishes)
__global__ void k_dinv() {
    int i = blockIdx.x * blockDim.x + threadIdx.x;
    if (i >= N_NODES) return;
    g_dinv[i] = rsqrtf((float)(g_cnt[i] + 1));
}

__global__ void k_fill(const void* __restrict__ ei) {
    int e = blockIdx.x * blockDim.x + threadIdx.x;
    if (e >= N_EDGES) return;
    int s = idx_at(ei, e);
    int d = idx_at(ei, (long long)N_EDGES + e);
    int pos = atomicAdd(&g_cur[d], 1);
    g_ci[pos] = s;
}

__device__ __forceinline__ uint32_t f2tf32(float f) {
    uint32_t u;
    asm("cvt.rna.tf32.f32 %0, %1;" : "=r"(u) : "f"(f));
    return u;
}

// W1^T -> tf32 bits (once, tiny)
__global__ void k_prep_w(const float* __restrict__ W1) {
    int t = blockIdx.x * blockDim.x + threadIdx.x;
    if (t >= HIDDEN * IN_FEAT) return;
    int n = t >> 9;          // 0..63
    int k = t & 511;         // 0..511
    g_w1t[t] = f2tf32(W1[(size_t)k * HIDDEN + n]);
}

__global__ void k_fold(const float* __restrict__ W2, const float* __restrict__ b2,
                       const float* __restrict__ fcw) {
    int f = threadIdx.x;
    if (f < HIDDEN) {
        float a = 0.f;
        #pragma unroll 8
        for (int j = 0; j < HIDDEN; j++) a += W2[f * HIDDEN + j] * fcw[j];
        g_w2f[f] = a;
    }
    if (f == 0) {
        float a = 0.f;
        for (int j = 0; j < HIDDEN; j++) a += b2[j] * fcw[j];
        g_bb = a;
    }
}

// ======================================================================
// GEMM1: mma.sync tf32, both A and B staged via cp.async (XOR swizzle).
// h1(fp16) = dinv * (X @ W1). CTA 128x64, 8 warps (4M x 2N).
// ======================================================================
#define GEMM_SMEM_BYTES ((8192 + 4096) * 4)   // A: 2*128*32 w, B: 2*64*32 w

__device__ __forceinline__ void cp16(uint32_t saddr, const void* g) {
    asm volatile("cp.async.cg.shared.global [%0], [%1], 16;" :: "r"(saddr), "l"(g));
}

__global__ __launch_bounds__(256) void k_gemm_mma(const float* __restrict__ X) {
    extern __shared__ uint32_t dsm[];
    uint32_t* As = dsm;            // [buf][row][32 w], XOR-swizzled 16B groups
    uint32_t* Bs = dsm + 8192;     // [buf][n][32 w], same swizzle
    uint32_t as_base = (uint32_t)__cvta_generic_to_shared(As);
    uint32_t bs_base = (uint32_t)__cvta_generic_to_shared(Bs);

    int tid = threadIdx.x;
    int lane = tid & 31;
    int wid = tid >> 5;
    int wm = wid & 3;
    int wn = wid >> 2;
    int block_row = blockIdx.x * 128;

    float acc[2][4][4];
    #pragma unroll
    for (int mi = 0; mi < 2; mi++)
        #pragma unroll
        for (int ni = 0; ni < 4; ni++)
            #pragma unroll
            for (int r = 0; r < 4; r++) acc[mi][ni][r] = 0.f;

    int lq = lane >> 2;
    int lr = lane & 3;

    auto issueA = [&](int ch, int buf) {
        #pragma unroll
        for (int i = 0; i < 4; i++) {
            int slot = tid + 256 * i;          // 0..1023
            int row = slot >> 3;
            int c4 = slot & 7;
            int sw = (c4 ^ (row & 7)) << 2;
            uint32_t widx = buf * 4096 + row * 32 + sw;
            int gr = block_row + row;
            if (gr < N_NODES) {
                cp16(as_base + widx * 4, &X[(size_t)gr * IN_FEAT + ch * 32 + c4 * 4]);
            } else {
                *(uint4*)&As[widx] = make_uint4(0, 0, 0, 0);
            }
        }
    };
    auto issueB = [&](int ch, int buf) {
        #pragma unroll
        for (int i = 0; i < 2; i++) {
            int slot = tid + 256 * i;          // 0..511
            int n = slot >> 3;                 // 0..63
            int c4 = slot & 7;
            int sw = (c4 ^ (n & 7)) << 2;
            uint32_t widx = buf * 2048 + n * 32 + sw;
            cp16(bs_base + widx * 4, &g_w1t[(size_t)n * IN_FEAT + ch * 32 + c4 * 4]);
        }
    };

    issueA(0, 0);
    issueB(0, 0);
    asm volatile("cp.async.commit_group;");

    for (int ch = 0; ch < 16; ch++) {
        int buf = ch & 1;
        if (ch + 1 < 16) {
            issueA(ch + 1, buf ^ 1);
            issueB(ch + 1, buf ^ 1);
            asm volatile("cp.async.commit_group;");
            asm volatile("cp.async.wait_group 1;");
        } else {
            asm volatile("cp.async.wait_group 0;");
        }
        __syncthreads();

        const uint32_t* Ab = As + buf * 4096;
        const uint32_t* Bb = Bs + buf * 2048;

        #pragma unroll
        for (int kk = 0; kk < 32; kk += 8) {
            uint32_t a[2][4], b[4][2];
            int g0 = kk >> 2;
            #pragma unroll
            for (int mi = 0; mi < 2; mi++) {
                int r0 = wm * 32 + mi * 16 + lq;
                int r1 = r0 + 8;
                int s0 = r0 & 7;
                a[mi][0] = Ab[r0 * 32 + (((g0) ^ s0) << 2) + lr];
                a[mi][1] = Ab[r1 * 32 + (((g0) ^ s0) << 2) + lr];
                a[mi][2] = Ab[r0 * 32 + (((g0 + 1) ^ s0) << 2) + lr];
                a[mi][3] = Ab[r1 * 32 + (((g0 + 1) ^ s0) << 2) + lr];
            }
            #pragma unroll
            for (int ni = 0; ni < 4; ni++) {
                int n = wn * 32 + ni * 8 + lq;
                int sn = n & 7;
                b[ni][0] = Bb[n * 32 + (((g0) ^ sn) << 2) + lr];
                b[ni][1] = Bb[n * 32 + (((g0 + 1) ^ sn) << 2) + lr];
            }
            #pragma unroll
            for (int mi = 0; mi < 2; mi++)
                #pragma unroll
                for (int ni = 0; ni < 4; ni++) {
                    asm volatile(
                        "mma.sync.aligned.m16n8k8.row.col.f32.tf32.tf32.f32 "
                        "{%0,%1,%2,%3}, {%4,%5,%6,%7}, {%8,%9}, {%0,%1,%2,%3};"
                        : "+f"(acc[mi][ni][0]), "+f"(acc[mi][ni][1]),
                          "+f"(acc[mi][ni][2]), "+f"(acc[mi][ni][3])
                        : "r"(a[mi][0]), "r"(a[mi][1]), "r"(a[mi][2]), "r"(a[mi][3]),
                          "r"(b[ni][0]), "r"(b[ni][1]));
                }
        }
        __syncthreads();
    }

    // ---- epilogue: scale by dinv, store fp16 to g_h1 ----
    __half2* h1h = (__half2*)g_h1;
    #pragma unroll
    for (int mi = 0; mi < 2; mi++) {
        int r0 = block_row + wm * 32 + mi * 16 + lq;
        int r1 = r0 + 8;
        float d0 = (r0 < N_NODES) ? g_dinv[r0] : 0.f;
        float d1 = (r1 < N_NODES) ? g_dinv[r1] : 0.f;
        #pragma unroll
        for (int ni = 0; ni < 4; ni++) {
            int c2 = wn * 16 + ni * 4 + lr;
            if (r0 < N_NODES)
                h1h[(size_t)r0 * 32 + c2] =
                    __floats2half2_rn(acc[mi][ni][0] * d0, acc[mi][ni][1] * d0);
            if (r1 < N_NODES)
                h1h[(size_t)r1 * 32 + c2] =
                    __floats2half2_rn(acc[mi][ni][2] * d1, acc[mi][ni][3] * d1);
        }
    }
}

// ---------------- layer1 aggregation fused with layer2 fold ----------------
__global__ __launch_bounds__(256) void k_agg1(const float* __restrict__ b1) {
    int gw = (blockIdx.x * blockDim.x + threadIdx.x) >> 5;
    int lane = threadIdx.x & 31;
    if (gw >= N_NODES) return;
    const __half2* hp = (const __half2*)g_h1;
    float2 acc = __half22float2(hp[(size_t)gw * 32 + lane]);   // self loop (prescaled)
    int s = g_rp[gw], e = g_rp[gw + 1];
    for (int base = s; base < e; base += 32) {
        int c = -1;
        if (base + lane < e) c = g_ci[base + lane];
        int m = min(32, e - base);
        for (int j = 0; j < m; j++) {
            int src = __shfl_sync(0xffffffffu, c, j);
            float2 v = __half22float2(hp[(size_t)src * 32 + lane]);
            acc.x += v.x;
            acc.y += v.y;
        }
    }
    float di = g_dinv[gw];
    float y0 = fmaxf(fmaf(di, acc.x, b1[2 * lane]), 0.f);
    float y1 = fmaxf(fmaf(di, acc.y, b1[2 * lane + 1]), 0.f);
    float p = y0 * g_w2f[2 * lane] + y1 * g_w2f[2 * lane + 1];
    #pragma unroll
    for (int o = 16; o; o >>= 1) p += __shfl_xor_sync(0xffffffffu, p, o);
    if (lane == 0) g_t[gw] = di * p;
}

// ---------------- scalar layer-2 aggregation + mean-pool accumulate ----------------
__global__ void k_agg2_pool(const void* __restrict__ batch) {
    int i = blockIdx.x * blockDim.x + threadIdx.x;
    if (i >= N_NODES) return;
    float s = g_t[i];                 // self loop
    int e0 = g_rp[i], e1 = g_rp[i + 1];
    for (int e = e0; e < e1; e++) s += g_t[g_ci[e]];
    float si = g_dinv[i] * s + g_bb;
    int b = idx_at(batch, i);
    atomicAdd(&g_gsum[b], si);
    atomicAdd(&g_gcnt[b], 1.0f);
}

__global__ void k_final(const float* __restrict__ fcb, float* __restrict__ out) {
    int g = blockIdx.x * blockDim.x + threadIdx.x;
    if (g >= N_GRAPHS) return;
    out[g] = g_gsum[g] / fmaxf(g_gcnt[g], 1.0f) + fcb[0];
}

// ---------------- launch ----------------
extern "C" void kernel_launch(void* const* d_in, const int* in_sizes, int n_in,
                              void* d_out, int out_size) {
    const float* x   = (const float*)d_in[0];
    const void*  ei  = d_in[1];
    const void*  bat = d_in[2];
    int base = (in_sizes[3] == IN_FEAT * HIDDEN) ? 3 : 4;
    const float* W1  = (const float*)d_in[base + 0];
    const float* b1  = (const float*)d_in[base + 1];
    const float* W2  = (const float*)d_in[base + 2];
    const float* b2  = (const float*)d_in[base + 3];
    const float* fcw = (const float*)d_in[base + 4];
    const float* fcb = (const float*)d_in[base + 5];
    float* out = (float*)d_out;

    const int SCAN_BLOCKS = (N_NODES + 1023) / 1024;   // 98

    static cudaStream_t s1 = 0;
    static cudaEvent_t evC = 0, evG = 0;
    if (s1 == 0) {
        cudaStreamCreateWithFlags(&s1, cudaStreamNonBlocking);
        cudaEventCreateWithFlags(&evC, cudaEventDisableTiming);
        cudaEventCreateWithFlags(&evG, cudaEventDisableTiming);
    }
    cudaFuncSetAttribute(k_gemm_mma, cudaFuncAttributeMaxDynamicSharedMemorySize,
                         GEMM_SMEM_BYTES);

    // ---- stream 0: CSR chain ----
    k_detect<<<1, 32>>>((const int*)ei);
    k_zero<<<(N_NODES + 255) / 256, 256>>>();
    k_count<<<(N_EDGES + 255) / 256, 256>>>(ei);
    cudaEventRecord(evC, 0);

    // ---- stream 1 (forked): dinv + weights prep + GEMM ----
    cudaStreamWaitEvent(s1, evC, 0);
    k_dinv<<<(N_NODES + 255) / 256, 256, 0, s1>>>();
    k_prep_w<<<(HIDDEN * IN_FEAT + 255) / 256, 256, 0, s1>>>(W1);
    k_fold<<<1, 64, 0, s1>>>(W2, b2, fcw);
    k_gemm_mma<<<(N_NODES + 127) / 128, 256, GEMM_SMEM_BYTES, s1>>>(x);
    cudaEventRecord(evG, s1);

    // ---- stream 0 continues: scan + fill (concurrent with GEMM) ----
    k_scan_a<<<SCAN_BLOCKS, 1024>>>();
    k_scan_b<<<1, 32>>>(SCAN_BLOCKS);
    k_scan_c<<<SCAN_BLOCKS, 1024>>>();
    k_fill<<<(N_EDGES + 255) / 256, 256>>>(ei);

    // ---- join, then aggregation ----
    cudaStreamWaitEvent(0, evG, 0);
    k_agg1<<<(N_NODES * 32 + 255) / 256, 256>>>(b1);
    k_agg2_pool<<<(N_NODES + 255) / 256, 256>>>(bat);
    k_final<<<(N_GRAPHS + 255) / 256, 256>>>(fcb, out);
}

// round 8
// speedup vs baseline: 1.5552x; 1.0042x over previous
#include <cuda_runtime.h>
#include <cuda_fp16.h>
#include <cuda_bf16.h>
#include <stdint.h>

#define N_NODES  100000
#define N_EDGES  3200000
#define IN_FEAT  512
#define HIDDEN   64
#define N_GRAPHS 2048

// ---------------- scratch (static device allocations) ----------------
__device__ __align__(16) __half g_h1[(size_t)N_NODES * HIDDEN]; // UNscaled X@W1, fp16
__device__ int   g_rp[N_NODES + 1];                // CSR row ptr (by dst)
__device__ int   g_cnt[N_NODES];                   // in-degree histogram
__device__ int   g_cur[N_NODES];                   // fill cursor
__device__ int   g_ci[N_EDGES];                    // CSR col idx (src)
__device__ float g_dinv[N_NODES];
__device__ float g_t[N_NODES];                     // per-node layer2 scalar
__device__ float g_w2f[HIDDEN];                    // W2 @ fc_w
__device__ float g_bb;                             // b2 . fc_w
__device__ float g_gsum[N_GRAPHS];
__device__ float g_gcnt[N_GRAPHS];
__device__ int   g_bsum[128];                      // scan block sums
__device__ int   g_is64;                           // 1 if index buffers are int64
__device__ __align__(16) uint32_t g_w1t[(size_t)HIDDEN * IN_FEAT]; // W1^T in tf32 bits

// ---------------- init: zero + dtype detect (merged) ----------------
__global__ void k_init(const int* __restrict__ ei32) {
    int i = blockIdx.x * blockDim.x + threadIdx.x;
    if (i < N_NODES) g_cnt[i] = 0;
    if (i < N_GRAPHS) { g_gsum[i] = 0.f; g_gcnt[i] = 0.f; }
    if (i == 0) {
        int s = 1;
        for (int j = 1; j < 512; j += 2) {
            if (ei32[j] != 0) { s = 0; break; }
        }
        g_is64 = s;
    }
}

__device__ __forceinline__ int idx_at(const void* p, long long i) {
    if (g_is64) return (int)((const long long*)p)[i];
    return ((const int*)p)[i];
}

// ---------------- histogram: 2 edges per thread ----------------
__global__ void k_count(const void* __restrict__ ei) {
    int e2 = (blockIdx.x * blockDim.x + threadIdx.x) * 2;
    if (e2 >= N_EDGES) return;
    int d0, d1;
    if (g_is64) {
        longlong2 v = ((const longlong2*)((const long long*)ei + N_EDGES))[e2 >> 1];
        d0 = (int)v.x; d1 = (int)v.y;
    } else {
        int2 v = ((const int2*)((const int*)ei + N_EDGES))[e2 >> 1];
        d0 = v.x; d1 = v.y;
    }
    atomicAdd(&g_cnt[d0], 1);
    atomicAdd(&g_cnt[d1], 1);
}

// dinv straight from histogram
__global__ void k_dinv() {
    int i = blockIdx.x * blockDim.x + threadIdx.x;
    if (i >= N_NODES) return;
    g_dinv[i] = rsqrtf((float)(g_cnt[i] + 1));
}

// ---------------- exclusive scan over g_cnt -> g_rp ----------------
__global__ void k_scan_a() {
    __shared__ int ws[32];
    int tid = threadIdx.x;
    int idx = blockIdx.x * 1024 + tid;
    int v = (idx < N_NODES) ? g_cnt[idx] : 0;
    int lane = tid & 31, w = tid >> 5;
    int s = v;
    #pragma unroll
    for (int o = 16; o; o >>= 1) s += __shfl_xor_sync(0xffffffffu, s, o);
    if (lane == 0) ws[w] = s;
    __syncthreads();
    if (w == 0) {
        int x = ws[lane];
        #pragma unroll
        for (int o = 16; o; o >>= 1) x += __shfl_xor_sync(0xffffffffu, x, o);
        if (lane == 0) g_bsum[blockIdx.x] = x;
    }
}

__global__ void k_scan_b(int nblocks) {
    if (threadIdx.x == 0) {
        int run = 0;
        for (int i = 0; i < nblocks; i++) { int t = g_bsum[i]; g_bsum[i] = run; run += t; }
    }
}

__global__ void k_scan_c() {
    __shared__ int ws[32];
    int tid = threadIdx.x;
    int idx = blockIdx.x * 1024 + tid;
    int v = (idx < N_NODES) ? g_cnt[idx] : 0;
    int lane = tid & 31, w = tid >> 5;
    int inc = v;
    #pragma unroll
    for (int o = 1; o < 32; o <<= 1) {
        int n = __shfl_up_sync(0xffffffffu, inc, o);
        if (lane >= o) inc += n;
    }
    if (lane == 31) ws[w] = inc;
    __syncthreads();
    if (w == 0) {
        int x = ws[lane];
        #pragma unroll
        for (int o = 1; o < 32; o <<= 1) {
            int n = __shfl_up_sync(0xffffffffu, x, o);
            if (lane >= o) x += n;
        }
        ws[lane] = x;
    }
    __syncthreads();
    int off = (w > 0) ? ws[w - 1] : 0;
    int excl = off + inc - v;
    if (idx < N_NODES) { g_rp[idx] = g_bsum[blockIdx.x] + excl; g_cur[idx] = g_bsum[blockIdx.x] + excl; }
    if (idx == 0 && blockIdx.x == 0) g_rp[N_NODES] = N_EDGES;
}

// ---------------- CSR fill: 2 edges per thread ----------------
__global__ void k_fill(const void* __restrict__ ei) {
    int e2 = (blockIdx.x * blockDim.x + threadIdx.x) * 2;
    if (e2 >= N_EDGES) return;
    int s0, s1, d0, d1;
    if (g_is64) {
        longlong2 sv = ((const longlong2*)ei)[e2 >> 1];
        longlong2 dv = ((const longlong2*)((const long long*)ei + N_EDGES))[e2 >> 1];
        s0 = (int)sv.x; s1 = (int)sv.y; d0 = (int)dv.x; d1 = (int)dv.y;
    } else {
        int2 sv = ((const int2*)ei)[e2 >> 1];
        int2 dv = ((const int2*)((const int*)ei + N_EDGES))[e2 >> 1];
        s0 = sv.x; s1 = sv.y; d0 = dv.x; d1 = dv.y;
    }
    g_ci[atomicAdd(&g_cur[d0], 1)] = s0;
    g_ci[atomicAdd(&g_cur[d1], 1)] = s1;
}

__device__ __forceinline__ uint32_t f2tf32(float f) {
    uint32_t u;
    asm("cvt.rna.tf32.f32 %0, %1;" : "=r"(u) : "f"(f));
    return u;
}

// ---------------- weights prep: W1^T tf32 + layer2 fold (merged) ----------------
__global__ void k_prep(const float* __restrict__ W1, const float* __restrict__ W2,
                       const float* __restrict__ b2, const float* __restrict__ fcw) {
    int t = blockIdx.x * blockDim.x + threadIdx.x;
    if (t < HIDDEN * IN_FEAT) {
        int n = t >> 9;          // 0..63
        int k = t & 511;         // 0..511
        g_w1t[t] = f2tf32(W1[(size_t)k * HIDDEN + n]);
    }
    if (blockIdx.x == 0 && threadIdx.x < HIDDEN) {
        int f = threadIdx.x;
        float a = 0.f;
        #pragma unroll 8
        for (int j = 0; j < HIDDEN; j++) a += W2[f * HIDDEN + j] * fcw[j];
        g_w2f[f] = a;
        if (f == 0) {
            float bb = 0.f;
            for (int j = 0; j < HIDDEN; j++) bb += b2[j] * fcw[j];
            g_bb = bb;
        }
    }
}

// ======================================================================
// GEMM1: mma.sync tf32, A and B staged via cp.async (XOR swizzle).
// h1(fp16, UNSCALED) = X @ W1. CTA 128x64, 8 warps (4M x 2N). No dinv dep.
// ======================================================================
#define GEMM_SMEM_BYTES ((8192 + 4096) * 4)   // A: 2*128*32 w, B: 2*64*32 w

__device__ __forceinline__ void cp16(uint32_t saddr, const void* g) {
    asm volatile("cp.async.cg.shared.global [%0], [%1], 16;" :: "r"(saddr), "l"(g));
}

__global__ __launch_bounds__(256) void k_gemm_mma(const float* __restrict__ X) {
    extern __shared__ uint32_t dsm[];
    uint32_t* As = dsm;            // [buf][row][32 w], XOR-swizzled 16B groups
    uint32_t* Bs = dsm + 8192;     // [buf][n][32 w], same swizzle
    uint32_t as_base = (uint32_t)__cvta_generic_to_shared(As);
    uint32_t bs_base = (uint32_t)__cvta_generic_to_shared(Bs);

    int tid = threadIdx.x;
    int lane = tid & 31;
    int wid = tid >> 5;
    int wm = wid & 3;
    int wn = wid >> 2;
    int block_row = blockIdx.x * 128;

    float acc[2][4][4];
    #pragma unroll
    for (int mi = 0; mi < 2; mi++)
        #pragma unroll
        for (int ni = 0; ni < 4; ni++)
            #pragma unroll
            for (int r = 0; r < 4; r++) acc[mi][ni][r] = 0.f;

    int lq = lane >> 2;
    int lr = lane & 3;

    auto issueA = [&](int ch, int buf) {
        #pragma unroll
        for (int i = 0; i < 4; i++) {
            int slot = tid + 256 * i;
            int row = slot >> 3;
            int c4 = slot & 7;
            int sw = (c4 ^ (row & 7)) << 2;
            uint32_t widx = buf * 4096 + row * 32 + sw;
            int gr = block_row + row;
            if (gr < N_NODES) {
                cp16(as_base + widx * 4, &X[(size_t)gr * IN_FEAT + ch * 32 + c4 * 4]);
            } else {
                *(uint4*)&As[widx] = make_uint4(0, 0, 0, 0);
            }
        }
    };
    auto issueB = [&](int ch, int buf) {
        #pragma unroll
        for (int i = 0; i < 2; i++) {
            int slot = tid + 256 * i;
            int n = slot >> 3;
            int c4 = slot & 7;
            int sw = (c4 ^ (n & 7)) << 2;
            uint32_t widx = buf * 2048 + n * 32 + sw;
            cp16(bs_base + widx * 4, &g_w1t[(size_t)n * IN_FEAT + ch * 32 + c4 * 4]);
        }
    };

    issueA(0, 0);
    issueB(0, 0);
    asm volatile("cp.async.commit_group;");

    for (int ch = 0; ch < 16; ch++) {
        int buf = ch & 1;
        if (ch + 1 < 16) {
            issueA(ch + 1, buf ^ 1);
            issueB(ch + 1, buf ^ 1);
            asm volatile("cp.async.commit_group;");
            asm volatile("cp.async.wait_group 1;");
        } else {
            asm volatile("cp.async.wait_group 0;");
        }
        __syncthreads();

        const uint32_t* Ab = As + buf * 4096;
        const uint32_t* Bb = Bs + buf * 2048;

        #pragma unroll
        for (int kk = 0; kk < 32; kk += 8) {
            uint32_t a[2][4], b[4][2];
            int g0 = kk >> 2;
            #pragma unroll
            for (int mi = 0; mi < 2; mi++) {
                int r0 = wm * 32 + mi * 16 + lq;
                int r1 = r0 + 8;
                int s0 = r0 & 7;
                a[mi][0] = Ab[r0 * 32 + (((g0) ^ s0) << 2) + lr];
                a[mi][1] = Ab[r1 * 32 + (((g0) ^ s0) << 2) + lr];
                a[mi][2] = Ab[r0 * 32 + (((g0 + 1) ^ s0) << 2) + lr];
                a[mi][3] = Ab[r1 * 32 + (((g0 + 1) ^ s0) << 2) + lr];
            }
            #pragma unroll
            for (int ni = 0; ni < 4; ni++) {
                int n = wn * 32 + ni * 8 + lq;
                int sn = n & 7;
                b[ni][0] = Bb[n * 32 + (((g0) ^ sn) << 2) + lr];
                b[ni][1] = Bb[n * 32 + (((g0 + 1) ^ sn) << 2) + lr];
            }
            #pragma unroll
            for (int mi = 0; mi < 2; mi++)
                #pragma unroll
                for (int ni = 0; ni < 4; ni++) {
                    asm volatile(
                        "mma.sync.aligned.m16n8k8.row.col.f32.tf32.tf32.f32 "
                        "{%0,%1,%2,%3}, {%4,%5,%6,%7}, {%8,%9}, {%0,%1,%2,%3};"
                        : "+f"(acc[mi][ni][0]), "+f"(acc[mi][ni][1]),
                          "+f"(acc[mi][ni][2]), "+f"(acc[mi][ni][3])
                        : "r"(a[mi][0]), "r"(a[mi][1]), "r"(a[mi][2]), "r"(a[mi][3]),
                          "r"(b[ni][0]), "r"(b[ni][1]));
                }
        }
        __syncthreads();
    }

    // ---- epilogue: store UNscaled fp16 h1 ----
    __half2* h1h = (__half2*)g_h1;
    #pragma unroll
    for (int mi = 0; mi < 2; mi++) {
        int r0 = block_row + wm * 32 + mi * 16 + lq;
        int r1 = r0 + 8;
        #pragma unroll
        for (int ni = 0; ni < 4; ni++) {
            int c2 = wn * 16 + ni * 4 + lr;
            if (r0 < N_NODES)
                h1h[(size_t)r0 * 32 + c2] =
                    __floats2half2_rn(acc[mi][ni][0], acc[mi][ni][1]);
            if (r1 < N_NODES)
                h1h[(size_t)r1 * 32 + c2] =
                    __floats2half2_rn(acc[mi][ni][2], acc[mi][ni][3]);
        }
    }
}

// ---------------- layer1 aggregation fused with layer2 fold ----------------
// warp per node: acc = sum_{src in N(i) ∪ {i}} dinv[src] * h1[src]
__global__ __launch_bounds__(256) void k_agg1(const float* __restrict__ b1) {
    int gw = (blockIdx.x * blockDim.x + threadIdx.x) >> 5;
    int lane = threadIdx.x & 31;
    if (gw >= N_NODES) return;
    const __half2* hp = (const __half2*)g_h1;
    float di = g_dinv[gw];
    float2 selfv = __half22float2(hp[(size_t)gw * 32 + lane]);
    float2 acc = make_float2(selfv.x * di, selfv.y * di);      // self loop
    int s = g_rp[gw], e = g_rp[gw + 1];
    for (int base = s; base < e; base += 32) {
        int c = 0; float dv = 0.f;
        if (base + lane < e) { c = g_ci[base + lane]; dv = g_dinv[c]; }
        int m = min(32, e - base);
        for (int j = 0; j < m; j++) {
            int src = __shfl_sync(0xffffffffu, c, j);
            float dj = __shfl_sync(0xffffffffu, dv, j);
            float2 v = __half22float2(hp[(size_t)src * 32 + lane]);
            acc.x = fmaf(v.x, dj, acc.x);
            acc.y = fmaf(v.y, dj, acc.y);
        }
    }
    float y0 = fmaxf(fmaf(di, acc.x, b1[2 * lane]), 0.f);
    float y1 = fmaxf(fmaf(di, acc.y, b1[2 * lane + 1]), 0.f);
    float p = y0 * g_w2f[2 * lane] + y1 * g_w2f[2 * lane + 1];
    #pragma unroll
    for (int o = 16; o; o >>= 1) p += __shfl_xor_sync(0xffffffffu, p, o);
    if (lane == 0) g_t[gw] = di * p;
}

// ---------------- scalar layer-2 aggregation + mean-pool accumulate ----------------
__global__ void k_agg2_pool(const void* __restrict__ batch) {
    int i = blockIdx.x * blockDim.x + threadIdx.x;
    if (i >= N_NODES) return;
    float s = g_t[i];                 // self loop
    int e0 = g_rp[i], e1 = g_rp[i + 1];
    for (int e = e0; e < e1; e++) s += g_t[g_ci[e]];
    float si = g_dinv[i] * s + g_bb;
    int b = idx_at(batch, i);
    atomicAdd(&g_gsum[b], si);
    atomicAdd(&g_gcnt[b], 1.0f);
}

__global__ void k_final(const float* __restrict__ fcb, float* __restrict__ out) {
    int g = blockIdx.x * blockDim.x + threadIdx.x;
    if (g >= N_GRAPHS) return;
    out[g] = g_gsum[g] / fmaxf(g_gcnt[g], 1.0f) + fcb[0];
}

// ---------------- launch ----------------
extern "C" void kernel_launch(void* const* d_in, const int* in_sizes, int n_in,
                              void* d_out, int out_size) {
    const float* x   = (const float*)d_in[0];
    const void*  ei  = d_in[1];
    const void*  bat = d_in[2];
    int base = (in_sizes[3] == IN_FEAT * HIDDEN) ? 3 : 4;
    const float* W1  = (const float*)d_in[base + 0];
    const float* b1  = (const float*)d_in[base + 1];
    const float* W2  = (const float*)d_in[base + 2];
    const float* b2  = (const float*)d_in[base + 3];
    const float* fcw = (const float*)d_in[base + 4];
    const float* fcb = (const float*)d_in[base + 5];
    float* out = (float*)d_out;

    const int SCAN_BLOCKS = (N_NODES + 1023) / 1024;   // 98

    static cudaStream_t s1 = 0;
    static cudaEvent_t evG = 0, evStart = 0;
    if (s1 == 0) {
        cudaStreamCreateWithFlags(&s1, cudaStreamNonBlocking);
        cudaEventCreateWithFlags(&evG, cudaEventDisableTiming);
        cudaEventCreateWithFlags(&evStart, cudaEventDisableTiming);
    }
    cudaFuncSetAttribute(k_gemm_mma, cudaFuncAttributeMaxDynamicSharedMemorySize,
                         GEMM_SMEM_BYTES);

    // fork point: stream1 starts GEMM branch immediately (no CSR dependency)
    cudaEventRecord(evStart, 0);
    cudaStreamWaitEvent(s1, evStart, 0);
    k_prep<<<(HIDDEN * IN_FEAT + 255) / 256, 256, 0, s1>>>(W1, W2, b2, fcw);
    k_gemm_mma<<<(N_NODES + 127) / 128, 256, GEMM_SMEM_BYTES, s1>>>(x);
    cudaEventRecord(evG, s1);

    // stream 0: CSR chain (concurrent with GEMM)
    k_init<<<(N_NODES + 255) / 256, 256>>>((const int*)ei);
    k_count<<<(N_EDGES / 2 + 255) / 256, 256>>>(ei);
    k_dinv<<<(N_NODES + 255) / 256, 256>>>();
    k_scan_a<<<SCAN_BLOCKS, 1024>>>();
    k_scan_b<<<1, 32>>>(SCAN_BLOCKS);
    k_scan_c<<<SCAN_BLOCKS, 1024>>>();
    k_fill<<<(N_EDGES / 2 + 255) / 256, 256>>>(ei);

    // join, then aggregation
    cudaStreamWaitEvent(0, evG, 0);
    k_agg1<<<(N_NODES * 32 + 255) / 256, 256>>>(b1);
    k_agg2_pool<<<(N_NODES + 255) / 256, 256>>>(bat);
    k_final<<<(N_GRAPHS + 255) / 256, 256>>>(fcb, out);
}

// round 9
// speedup vs baseline: 1.5623x; 1.0045x over previous
#include <cuda_runtime.h>
#include <cuda_fp16.h>
#include <cuda_bf16.h>
#include <stdint.h>

#define N_NODES  100000
#define N_EDGES  3200000
#define IN_FEAT  512
#define HIDDEN   64
#define N_GRAPHS 2048

// ---------------- scratch (static device allocations) ----------------
__device__ __align__(16) __half g_h1[(size_t)N_NODES * HIDDEN]; // UNscaled X@W1, fp16
__device__ int   g_rp[N_NODES + 1];                // CSR row ptr (by dst)
__device__ int   g_cnt[N_NODES];                   // in-degree histogram
__device__ int   g_cur[N_NODES];                   // fill cursor
__device__ int   g_ci[N_EDGES];                    // CSR col idx (src)
__device__ float g_dinv[N_NODES];
__device__ float g_t[N_NODES];                     // per-node layer2 scalar
__device__ float g_w2f[HIDDEN];                    // W2 @ fc_w
__device__ float g_bb;                             // b2 . fc_w
__device__ float g_gsum[N_GRAPHS];
__device__ float g_gcnt[N_GRAPHS];
__device__ int   g_bsum[128];                      // scan block sums
__device__ int   g_is64;                           // 1 if index buffers are int64
__device__ __align__(16) uint32_t g_w1t[(size_t)HIDDEN * IN_FEAT]; // W1^T in tf32 bits

// ---------------- init: zero + dtype detect (merged) ----------------
__global__ void k_init(const int* __restrict__ ei32) {
    int i = blockIdx.x * blockDim.x + threadIdx.x;
    if (i < N_NODES) g_cnt[i] = 0;
    if (i < N_GRAPHS) { g_gsum[i] = 0.f; g_gcnt[i] = 0.f; }
    if (i == 0) {
        int s = 1;
        for (int j = 1; j < 512; j += 2) {
            if (ei32[j] != 0) { s = 0; break; }
        }
        g_is64 = s;
    }
}

__device__ __forceinline__ int idx_at(const void* p, long long i) {
    if (g_is64) return (int)((const long long*)p)[i];
    return ((const int*)p)[i];
}

// ---------------- histogram: 2 edges per thread ----------------
__global__ void k_count(const void* __restrict__ ei) {
    int e2 = (blockIdx.x * blockDim.x + threadIdx.x) * 2;
    if (e2 >= N_EDGES) return;
    int d0, d1;
    if (g_is64) {
        longlong2 v = ((const longlong2*)((const long long*)ei + N_EDGES))[e2 >> 1];
        d0 = (int)v.x; d1 = (int)v.y;
    } else {
        int2 v = ((const int2*)((const int*)ei + N_EDGES))[e2 >> 1];
        d0 = v.x; d1 = v.y;
    }
    atomicAdd(&g_cnt[d0], 1);
    atomicAdd(&g_cnt[d1], 1);
}

// ---------------- exclusive scan over g_cnt -> g_rp ----------------
__global__ void k_scan_a() {
    __shared__ int ws[32];
    int tid = threadIdx.x;
    int idx = blockIdx.x * 1024 + tid;
    int v = (idx < N_NODES) ? g_cnt[idx] : 0;
    int lane = tid & 31, w = tid >> 5;
    int s = v;
    #pragma unroll
    for (int o = 16; o; o >>= 1) s += __shfl_xor_sync(0xffffffffu, s, o);
    if (lane == 0) ws[w] = s;
    __syncthreads();
    if (w == 0) {
        int x = ws[lane];
        #pragma unroll
        for (int o = 16; o; o >>= 1) x += __shfl_xor_sync(0xffffffffu, x, o);
        if (lane == 0) g_bsum[blockIdx.x] = x;
    }
}

__global__ void k_scan_b(int nblocks) {
    if (threadIdx.x == 0) {
        int run = 0;
        for (int i = 0; i < nblocks; i++) { int t = g_bsum[i]; g_bsum[i] = run; run += t; }
    }
}

// scan_c also computes dinv (merged)
__global__ void k_scan_c() {
    __shared__ int ws[32];
    int tid = threadIdx.x;
    int idx = blockIdx.x * 1024 + tid;
    int v = (idx < N_NODES) ? g_cnt[idx] : 0;
    int lane = tid & 31, w = tid >> 5;
    int inc = v;
    #pragma unroll
    for (int o = 1; o < 32; o <<= 1) {
        int n = __shfl_up_sync(0xffffffffu, inc, o);
        if (lane >= o) inc += n;
    }
    if (lane == 31) ws[w] = inc;
    __syncthreads();
    if (w == 0) {
        int x = ws[lane];
        #pragma unroll
        for (int o = 1; o < 32; o <<= 1) {
            int n = __shfl_up_sync(0xffffffffu, x, o);
            if (lane >= o) x += n;
        }
        ws[lane] = x;
    }
    __syncthreads();
    int off = (w > 0) ? ws[w - 1] : 0;
    int excl = off + inc - v;
    if (idx < N_NODES) {
        int p = g_bsum[blockIdx.x] + excl;
        g_rp[idx] = p;
        g_cur[idx] = p;
        g_dinv[idx] = rsqrtf((float)(v + 1));
    }
    if (idx == 0 && blockIdx.x == 0) g_rp[N_NODES] = N_EDGES;
}

// ---------------- CSR fill: 2 edges per thread ----------------
__global__ void k_fill(const void* __restrict__ ei) {
    int e2 = (blockIdx.x * blockDim.x + threadIdx.x) * 2;
    if (e2 >= N_EDGES) return;
    int s0, s1, d0, d1;
    if (g_is64) {
        longlong2 sv = ((const longlong2*)ei)[e2 >> 1];
        longlong2 dv = ((const longlong2*)((const long long*)ei + N_EDGES))[e2 >> 1];
        s0 = (int)sv.x; s1 = (int)sv.y; d0 = (int)dv.x; d1 = (int)dv.y;
    } else {
        int2 sv = ((const int2*)ei)[e2 >> 1];
        int2 dv = ((const int2*)((const int*)ei + N_EDGES))[e2 >> 1];
        s0 = sv.x; s1 = sv.y; d0 = dv.x; d1 = dv.y;
    }
    g_ci[atomicAdd(&g_cur[d0], 1)] = s0;
    g_ci[atomicAdd(&g_cur[d1], 1)] = s1;
}

__device__ __forceinline__ uint32_t f2tf32(float f) {
    uint32_t u;
    asm("cvt.rna.tf32.f32 %0, %1;" : "=r"(u) : "f"(f));
    return u;
}

// ---------------- weights prep: W1^T tf32 + layer2 fold (merged) ----------------
__global__ void k_prep(const float* __restrict__ W1, const float* __restrict__ W2,
                       const float* __restrict__ b2, const float* __restrict__ fcw) {
    int t = blockIdx.x * blockDim.x + threadIdx.x;
    if (t < HIDDEN * IN_FEAT) {
        int n = t >> 9;          // 0..63
        int k = t & 511;         // 0..511
        g_w1t[t] = f2tf32(W1[(size_t)k * HIDDEN + n]);
    }
    if (blockIdx.x == 0 && threadIdx.x < HIDDEN) {
        int f = threadIdx.x;
        float a = 0.f;
        #pragma unroll 8
        for (int j = 0; j < HIDDEN; j++) a += W2[f * HIDDEN + j] * fcw[j];
        g_w2f[f] = a;
        if (f == 0) {
            float bb = 0.f;
            for (int j = 0; j < HIDDEN; j++) bb += b2[j] * fcw[j];
            g_bb = bb;
        }
    }
}

// ======================================================================
// GEMM1: mma.sync tf32. Full B (W1^T, 128KB) resident in smem; A streamed
// through a 3-stage cp.async ring. h1(fp16, unscaled) = X @ W1.
// CTA 128x64, 8 warps (4M x 2N).
// ======================================================================
#define A_STAGE_W 4096                       // 128 rows * 32 words
#define B_CHUNK_W 2048                       // 64 n * 32 words
#define GEMM_SMEM_BYTES ((3 * A_STAGE_W + 16 * B_CHUNK_W) * 4)   // 180224 B

__device__ __forceinline__ void cp16(uint32_t saddr, const void* g) {
    asm volatile("cp.async.cg.shared.global [%0], [%1], 16;" :: "r"(saddr), "l"(g));
}

__global__ __launch_bounds__(256) void k_gemm_mma(const float* __restrict__ X) {
    extern __shared__ uint32_t dsm[];
    uint32_t* As = dsm;                       // 3 stages
    uint32_t* Bs = dsm + 3 * A_STAGE_W;       // 16 chunk slabs
    uint32_t as_base = (uint32_t)__cvta_generic_to_shared(As);
    uint32_t bs_base = (uint32_t)__cvta_generic_to_shared(Bs);

    int tid = threadIdx.x;
    int lane = tid & 31;
    int wid = tid >> 5;
    int wm = wid & 3;
    int wn = wid >> 2;
    int block_row = blockIdx.x * 128;

    float acc[2][4][4];
    #pragma unroll
    for (int mi = 0; mi < 2; mi++)
        #pragma unroll
        for (int ni = 0; ni < 4; ni++)
            #pragma unroll
            for (int r = 0; r < 4; r++) acc[mi][ni][r] = 0.f;

    int lq = lane >> 2;
    int lr = lane & 3;

    auto issueA = [&](int ch, int stage) {
        #pragma unroll
        for (int i = 0; i < 4; i++) {
            int slot = tid + 256 * i;
            int row = slot >> 3;
            int c4 = slot & 7;
            int sw = (c4 ^ (row & 7)) << 2;
            uint32_t widx = stage * A_STAGE_W + row * 32 + sw;
            int gr = block_row + row;
            if (gr < N_NODES) {
                cp16(as_base + widx * 4, &X[(size_t)gr * IN_FEAT + ch * 32 + c4 * 4]);
            } else {
                *(uint4*)&As[widx] = make_uint4(0, 0, 0, 0);
            }
        }
    };

    // ---- preload ALL of B as one cp.async group (32 cp16 per thread) ----
    #pragma unroll
    for (int i = 0; i < 32; i++) {
        int slot = tid + 256 * i;             // 0..8191
        int ch = slot >> 9;                   // 0..15
        int r = slot & 511;
        int n = r >> 3;                       // 0..63
        int c4 = r & 7;
        int sw = (c4 ^ (n & 7)) << 2;
        uint32_t widx = ch * B_CHUNK_W + n * 32 + sw;
        cp16(bs_base + widx * 4, &g_w1t[(size_t)n * IN_FEAT + ch * 32 + c4 * 4]);
    }
    asm volatile("cp.async.commit_group;");   // G0 = B
    issueA(0, 0);
    asm volatile("cp.async.commit_group;");   // G1 = A0
    issueA(1, 1);
    asm volatile("cp.async.commit_group;");   // G2 = A1

    for (int ch = 0; ch < 16; ch++) {
        if (ch + 2 < 16) {
            issueA(ch + 2, (ch + 2) % 3);
            asm volatile("cp.async.commit_group;");
            asm volatile("cp.async.wait_group 2;");
        } else {
            asm volatile("cp.async.wait_group 0;");
        }
        __syncthreads();

        const uint32_t* Ab = As + (ch % 3) * A_STAGE_W;
        const uint32_t* Bb = Bs + ch * B_CHUNK_W;

        #pragma unroll
        for (int kk = 0; kk < 32; kk += 8) {
            uint32_t a[2][4], b[4][2];
            int g0 = kk >> 2;
            #pragma unroll
            for (int mi = 0; mi < 2; mi++) {
                int r0 = wm * 32 + mi * 16 + lq;
                int r1 = r0 + 8;
                int s0 = r0 & 7;
                a[mi][0] = Ab[r0 * 32 + (((g0) ^ s0) << 2) + lr];
                a[mi][1] = Ab[r1 * 32 + (((g0) ^ s0) << 2) + lr];
                a[mi][2] = Ab[r0 * 32 + (((g0 + 1) ^ s0) << 2) + lr];
                a[mi][3] = Ab[r1 * 32 + (((g0 + 1) ^ s0) << 2) + lr];
            }
            #pragma unroll
            for (int ni = 0; ni < 4; ni++) {
                int n = wn * 32 + ni * 8 + lq;
                int sn = n & 7;
                b[ni][0] = Bb[n * 32 + (((g0) ^ sn) << 2) + lr];
                b[ni][1] = Bb[n * 32 + (((g0 + 1) ^ sn) << 2) + lr];
            }
            #pragma unroll
            for (int mi = 0; mi < 2; mi++)
                #pragma unroll
                for (int ni = 0; ni < 4; ni++) {
                    asm volatile(
                        "mma.sync.aligned.m16n8k8.row.col.f32.tf32.tf32.f32 "
                        "{%0,%1,%2,%3}, {%4,%5,%6,%7}, {%8,%9}, {%0,%1,%2,%3};"
                        : "+f"(acc[mi][ni][0]), "+f"(acc[mi][ni][1]),
                          "+f"(acc[mi][ni][2]), "+f"(acc[mi][ni][3])
                        : "r"(a[mi][0]), "r"(a[mi][1]), "r"(a[mi][2]), "r"(a[mi][3]),
                          "r"(b[ni][0]), "r"(b[ni][1]));
                }
        }
        __syncthreads();
    }

    // ---- epilogue: store UNscaled fp16 h1 ----
    __half2* h1h = (__half2*)g_h1;
    #pragma unroll
    for (int mi = 0; mi < 2; mi++) {
        int r0 = block_row + wm * 32 + mi * 16 + lq;
        int r1 = r0 + 8;
        #pragma unroll
        for (int ni = 0; ni < 4; ni++) {
            int c2 = wn * 16 + ni * 4 + lr;
            if (r0 < N_NODES)
                h1h[(size_t)r0 * 32 + c2] =
                    __floats2half2_rn(acc[mi][ni][0], acc[mi][ni][1]);
            if (r1 < N_NODES)
                h1h[(size_t)r1 * 32 + c2] =
                    __floats2half2_rn(acc[mi][ni][2], acc[mi][ni][3]);
        }
    }
}

// ---------------- layer1 aggregation fused with layer2 fold ----------------
// warp per node: acc = sum_{src in N(i) ∪ {i}} dinv[src] * h1[src]
__global__ __launch_bounds__(256) void k_agg1(const float* __restrict__ b1) {
    int gw = (blockIdx.x * blockDim.x + threadIdx.x) >> 5;
    int lane = threadIdx.x & 31;
    if (gw >= N_NODES) return;
    const __half2* hp = (const __half2*)g_h1;
    float di = g_dinv[gw];
    float2 selfv = __half22float2(hp[(size_t)gw * 32 + lane]);
    float2 acc = make_float2(selfv.x * di, selfv.y * di);      // self loop
    int s = g_rp[gw], e = g_rp[gw + 1];
    int base = s;
    // full 32-edge groups: unrolled inner loop (batched loads)
    for (; base + 32 <= e; base += 32) {
        int c = g_ci[base + lane];
        float dv = g_dinv[c];
        #pragma unroll
        for (int j = 0; j < 32; j++) {
            int src = __shfl_sync(0xffffffffu, c, j);
            float dj = __shfl_sync(0xffffffffu, dv, j);
            float2 v = __half22float2(hp[(size_t)src * 32 + lane]);
            acc.x = fmaf(v.x, dj, acc.x);
            acc.y = fmaf(v.y, dj, acc.y);
        }
    }
    // remainder
    if (base < e) {
        int c = 0; float dv = 0.f;
        if (base + lane < e) { c = g_ci[base + lane]; dv = g_dinv[c]; }
        int m = e - base;
        for (int j = 0; j < m; j++) {
            int src = __shfl_sync(0xffffffffu, c, j);
            float dj = __shfl_sync(0xffffffffu, dv, j);
            float2 v = __half22float2(hp[(size_t)src * 32 + lane]);
            acc.x = fmaf(v.x, dj, acc.x);
            acc.y = fmaf(v.y, dj, acc.y);
        }
    }
    float y0 = fmaxf(fmaf(di, acc.x, b1[2 * lane]), 0.f);
    float y1 = fmaxf(fmaf(di, acc.y, b1[2 * lane + 1]), 0.f);
    float p = y0 * g_w2f[2 * lane] + y1 * g_w2f[2 * lane + 1];
    #pragma unroll
    for (int o = 16; o; o >>= 1) p += __shfl_xor_sync(0xffffffffu, p, o);
    if (lane == 0) g_t[gw] = di * p;
}

// ---------------- scalar layer-2 aggregation + mean-pool accumulate ----------------
__global__ void k_agg2_pool(const void* __restrict__ batch) {
    int i = blockIdx.x * blockDim.x + threadIdx.x;
    if (i >= N_NODES) return;
    float s = g_t[i];                 // self loop
    int e0 = g_rp[i], e1 = g_rp[i + 1];
    for (int e = e0; e < e1; e++) s += g_t[g_ci[e]];
    float si = g_dinv[i] * s + g_bb;
    int b = idx_at(batch, i);
    atomicAdd(&g_gsum[b], si);
    atomicAdd(&g_gcnt[b], 1.0f);
}

__global__ void k_final(const float* __restrict__ fcb, float* __restrict__ out) {
    int g = blockIdx.x * blockDim.x + threadIdx.x;
    if (g >= N_GRAPHS) return;
    out[g] = g_gsum[g] / fmaxf(g_gcnt[g], 1.0f) + fcb[0];
}

// ---------------- launch ----------------
extern "C" void kernel_launch(void* const* d_in, const int* in_sizes, int n_in,
                              void* d_out, int out_size) {
    const float* x   = (const float*)d_in[0];
    const void*  ei  = d_in[1];
    const void*  bat = d_in[2];
    int base = (in_sizes[3] == IN_FEAT * HIDDEN) ? 3 : 4;
    const float* W1  = (const float*)d_in[base + 0];
    const float* b1  = (const float*)d_in[base + 1];
    const float* W2  = (const float*)d_in[base + 2];
    const float* b2  = (const float*)d_in[base + 3];
    const float* fcw = (const float*)d_in[base + 4];
    const float* fcb = (const float*)d_in[base + 5];
    float* out = (float*)d_out;

    const int SCAN_BLOCKS = (N_NODES + 1023) / 1024;   // 98

    static cudaStream_t s1 = 0;
    static cudaEvent_t evG = 0, evStart = 0;
    if (s1 == 0) {
        cudaStreamCreateWithFlags(&s1, cudaStreamNonBlocking);
        cudaEventCreateWithFlags(&evG, cudaEventDisableTiming);
        cudaEventCreateWithFlags(&evStart, cudaEventDisableTiming);
    }
    cudaFuncSetAttribute(k_gemm_mma, cudaFuncAttributeMaxDynamicSharedMemorySize,
                         GEMM_SMEM_BYTES);

    // fork point: stream1 starts GEMM branch immediately (no CSR dependency)
    cudaEventRecord(evStart, 0);
    cudaStreamWaitEvent(s1, evStart, 0);
    k_prep<<<(HIDDEN * IN_FEAT + 255) / 256, 256, 0, s1>>>(W1, W2, b2, fcw);
    k_gemm_mma<<<(N_NODES + 127) / 128, 256, GEMM_SMEM_BYTES, s1>>>(x);
    cudaEventRecord(evG, s1);

    // stream 0: CSR chain (concurrent with GEMM)
    k_init<<<(N_NODES + 255) / 256, 256>>>((const int*)ei);
    k_count<<<(N_EDGES / 2 + 255) / 256, 256>>>(ei);
    k_scan_a<<<SCAN_BLOCKS, 1024>>>();
    k_scan_b<<<1, 32>>>(SCAN_BLOCKS);
    k_scan_c<<<SCAN_BLOCKS, 1024>>>();
    k_fill<<<(N_EDGES / 2 + 255) / 256, 256>>>(ei);

    // join, then aggregation
    cudaStreamWaitEvent(0, evG, 0);
    k_agg1<<<(N_NODES * 32 + 255) / 256, 256>>>(b1);
    k_agg2_pool<<<(N_NODES + 255) / 256, 256>>>(bat);
    k_final<<<(N_GRAPHS + 255) / 256, 256>>>(fcb, out);
}